// round 10
// baseline (speedup 1.0000x reference)
#include <cuda_runtime.h>
#include <cuda_bf16.h>
#include <cstdint>

#define BATCH 4
#define SEQ   2048
#define DIN   1024
#define DOUT  1024
#define MTOT  (BATCH * SEQ)
#define NEGC  (-1000000000.0f)

// ===========================================================================
// Scratch (device globals — allocations are forbidden)
// ===========================================================================
__device__ __nv_bfloat16 gx_hi[(size_t)MTOT * DIN];
__device__ __nv_bfloat16 gx_lo[(size_t)MTOT * DIN];
__device__ __nv_bfloat16 gw_hi[(size_t)3 * DOUT * DIN];
__device__ __nv_bfloat16 gw_lo[(size_t)3 * DOUT * DIN];
__device__ __nv_bfloat16 gq_hi[(size_t)MTOT * DOUT];
__device__ __nv_bfloat16 gq_lo[(size_t)MTOT * DOUT];
__device__ __nv_bfloat16 gk_hi[(size_t)MTOT * DOUT];
__device__ __nv_bfloat16 gk_lo[(size_t)MTOT * DOUT];
__device__ float         gv_f [(size_t)MTOT * DOUT];
__device__ __nv_bfloat16 gvt_hi[(size_t)BATCH * DOUT * SEQ];
__device__ __nv_bfloat16 gvt_lo[(size_t)BATCH * DOUT * SEQ];
__device__ float         gs_f [(size_t)BATCH * SEQ * SEQ];
__device__ __nv_bfloat16 gp_hi[(size_t)BATCH * SEQ * SEQ];
__device__ __nv_bfloat16 gp_lo[(size_t)BATCH * SEQ * SEQ];

// ===========================================================================
// Base-target PTX helpers (NO tcgen05 — harness compiles for sm_103 base)
// ===========================================================================
__device__ __forceinline__ uint32_t smem_u32(const void* p) {
    uint32_t a;
    asm("{ .reg .u64 t; cvta.to.shared.u64 t, %1; cvt.u32.u64 %0, t; }"
        : "=r"(a) : "l"(p));
    return a;
}

#define CP_ASYNC16(dst, src) \
    asm volatile("cp.async.cg.shared.global [%0], [%1], 16;" \
        :: "r"(dst), "l"(src))
#define CP_COMMIT()  asm volatile("cp.async.commit_group;" ::: "memory")
#define CP_WAIT(N)   asm volatile("cp.async.wait_group %0;" :: "n"(N) : "memory")

__device__ __forceinline__ void ldsm4(uint32_t* r, uint32_t addr) {
    asm volatile("ldmatrix.sync.aligned.m8n8.x4.shared.b16 {%0,%1,%2,%3}, [%4];"
        : "=r"(r[0]), "=r"(r[1]), "=r"(r[2]), "=r"(r[3]) : "r"(addr));
}

__device__ __forceinline__ void mma_bf16(float* c, const uint32_t* a, const uint32_t* b) {
    asm volatile(
        "mma.sync.aligned.m16n8k16.row.col.f32.bf16.bf16.f32 "
        "{%0,%1,%2,%3}, {%4,%5,%6,%7}, {%8,%9}, {%0,%1,%2,%3};"
        : "+f"(c[0]), "+f"(c[1]), "+f"(c[2]), "+f"(c[3])
        : "r"(a[0]), "r"(a[1]), "r"(a[2]), "r"(a[3]), "r"(b[0]), "r"(b[1]));
}

// ===========================================================================
// Shared GEMM engine: 128x128 CTA tile, 16 warps (4m x 4n, 32x32 warp tile),
// BK=64, 3-stage cp.async pipeline, SW128 XOR swizzle, bf16x3 split precision.
// SMEM per stage: A_hi | A_lo | B_hi | B_lo, each 128 rows x 128B = 16KB.
// 512 threads -> 4 warps/SMSP for latency hiding; ~100 regs/thread.
// ===========================================================================
#define NTHREADS    512
#define SUB_BYTES   16384
#define STAGE_BYTES 65536
#define NSTAGE      3
#define SMEM_BYTES  (NSTAGE * STAGE_BYTES)    // 196608

__device__ __forceinline__ void fill_stage(
    uint32_t sb, int stage,
    const __nv_bfloat16* aHi, const __nv_bfloat16* aLo, size_t strideA,
    const __nv_bfloat16* bHi, const __nv_bfloat16* bLo, size_t strideB,
    int k0, int tid)
{
    uint32_t base = sb + stage * STAGE_BYTES;
    #pragma unroll
    for (int sub = 0; sub < 4; sub++) {
        const __nv_bfloat16* src = (sub == 0) ? aHi : (sub == 1) ? aLo
                                 : (sub == 2) ? bHi : bLo;
        size_t stride = (sub < 2) ? strideA : strideB;
        uint32_t dst = base + sub * SUB_BYTES;
        #pragma unroll
        for (int t = 0; t < 2; t++) {
            int idx = tid + NTHREADS * t;        // [0,1024)
            int r = idx >> 3;                    // row 0..127
            int c = idx & 7;                     // 16B chunk 0..7
            uint32_t d = dst + (uint32_t)(r * 128 + ((c ^ (r & 7)) << 4));
            const void* g = src + (size_t)r * stride + k0 + c * 8;
            CP_ASYNC16(d, g);
        }
    }
    CP_COMMIT();
}

// Compute one stage (4 k16-steps, 3 split passes) into acc[2][4][4].
__device__ __forceinline__ void compute_stage(
    uint32_t sb, int stage, float acc[2][4][4], int wid, int lane)
{
    uint32_t base = sb + stage * STAGE_BYTES;
    const int wm = (wid & 3) * 32;
    const int wn = (wid >> 2) * 32;
    #pragma unroll
    for (int ks = 0; ks < 4; ks++) {
        uint32_t aH[2][4], aL[2][4], bH[4][2], bL[4][2];
        #pragma unroll
        for (int i = 0; i < 2; i++) {
            int row = wm + i * 16 + (lane & 15);
            int cb  = ks * 2 + (lane >> 4);
            uint32_t ad = base + (uint32_t)(row * 128 + ((cb ^ (row & 7)) << 4));
            ldsm4(aH[i], ad);
            ldsm4(aL[i], ad + SUB_BYTES);
        }
        // B: two n-tiles per ldmatrix.x4 (lane groups of 8 pick tile/k-half)
        #pragma unroll
        for (int jp = 0; jp < 2; jp++) {
            int g   = lane >> 3;                         // 0..3
            int row = wn + (jp * 2 + (g >> 1)) * 8 + (lane & 7);
            int cb  = ks * 2 + (g & 1);
            uint32_t bd = base + 2 * SUB_BYTES
                        + (uint32_t)(row * 128 + ((cb ^ (row & 7)) << 4));
            uint32_t t[4];
            ldsm4(t, bd);
            bH[jp*2][0] = t[0]; bH[jp*2][1] = t[1];
            bH[jp*2+1][0] = t[2]; bH[jp*2+1][1] = t[3];
            ldsm4(t, bd + SUB_BYTES);
            bL[jp*2][0] = t[0]; bL[jp*2][1] = t[1];
            bL[jp*2+1][0] = t[2]; bL[jp*2+1][1] = t[3];
        }
        #pragma unroll
        for (int i = 0; i < 2; i++)
            #pragma unroll
            for (int j = 0; j < 4; j++) {
                mma_bf16(acc[i][j], aH[i], bH[j]);
                mma_bf16(acc[i][j], aH[i], bL[j]);
                mma_bf16(acc[i][j], aL[i], bH[j]);
            }
    }
}

// Full K loop, 3-stage pipeline, one barrier per iteration.
__device__ __forceinline__ void gemm_mainloop(
    uint32_t sb, int nch,
    const __nv_bfloat16* aHi, const __nv_bfloat16* aLo, size_t strideA,
    const __nv_bfloat16* bHi, const __nv_bfloat16* bLo, size_t strideB,
    float acc[2][4][4], int tid, int wid, int lane)
{
    fill_stage(sb, 0, aHi, aLo, strideA, bHi, bLo, strideB, 0, tid);
    if (nch > 1)
        fill_stage(sb, 1, aHi, aLo, strideA, bHi, bLo, strideB, 64, tid);

    int stage = 0;
    for (int ch = 0; ch < nch; ch++) {
        if (ch + 1 < nch) CP_WAIT(1); else CP_WAIT(0);
        __syncthreads();
        compute_stage(sb, stage, acc, wid, lane);
        int nf = ch + 2;
        if (nf < nch) {
            int fs = stage + 2; if (fs >= NSTAGE) fs -= NSTAGE;
            fill_stage(sb, fs, aHi, aLo, strideA, bHi, bLo, strideB, nf * 64, tid);
        }
        if (++stage == NSTAGE) stage = 0;
    }
}

// ===========================================================================
// Kernel: merged split fp32 -> bf16 (hi, lo) for x, Wq, Wk, Wv (one launch)
// ===========================================================================
__global__ __launch_bounds__(256) void split_all_kernel(
    const float* __restrict__ x,  const float* __restrict__ Wq,
    const float* __restrict__ Wk, const float* __restrict__ Wv)
{
    const int nx = MTOT * DIN;
    const int nw = DOUT * DIN;
    int i = blockIdx.x * 256 + threadIdx.x;
    const float* src; __nv_bfloat16 *hi, *lo; int idx;
    if (i < nx) {
        src = x; idx = i; hi = gx_hi; lo = gx_lo;
    } else {
        int t = i - nx;
        int z = t / nw;
        idx = t - z * nw;
        src = (z == 0) ? Wq : (z == 1) ? Wk : Wv;
        hi = gw_hi + (size_t)z * nw;
        lo = gw_lo + (size_t)z * nw;
    }
    float f = src[idx];
    __nv_bfloat16 h = __float2bfloat16(f);
    hi[idx] = h;
    lo[idx] = __float2bfloat16(f - __bfloat162float(h));
}

// ===========================================================================
// Kernel: QKV projection.  z selects Q/K/V.
// ===========================================================================
__global__ __launch_bounds__(NTHREADS, 1) void qkv_mma(
    const float* __restrict__ bq, const float* __restrict__ bk,
    const float* __restrict__ bv)
{
    extern __shared__ char smem[];
    const uint32_t sb = smem_u32(smem);
    const int tid = threadIdx.x, wid = tid >> 5, lane = tid & 31;
    const int z = blockIdx.z;
    const int m0 = blockIdx.y * 128;
    const int n0 = blockIdx.x * 128;

    const __nv_bfloat16* aHi = gx_hi + (size_t)m0 * DIN;
    const __nv_bfloat16* aLo = gx_lo + (size_t)m0 * DIN;
    size_t woff = (size_t)z * DOUT * DIN + (size_t)n0 * DIN;
    const __nv_bfloat16* bHi = gw_hi + woff;
    const __nv_bfloat16* bLo = gw_lo + woff;
    const float* bias = (z == 0) ? bq : (z == 1) ? bk : bv;

    float acc[2][4][4];
    #pragma unroll
    for (int i = 0; i < 2; i++)
        #pragma unroll
        for (int j = 0; j < 4; j++)
            #pragma unroll
            for (int v = 0; v < 4; v++) acc[i][j][v] = 0.0f;

    gemm_mainloop(sb, DIN / 64, aHi, aLo, DIN, bHi, bLo, DIN, acc, tid, wid, lane);

    const int wm = (wid & 3) * 32, wn = (wid >> 2) * 32;
    #pragma unroll
    for (int i = 0; i < 2; i++) {
        #pragma unroll
        for (int j = 0; j < 4; j++) {
            int col = n0 + wn + j * 8 + (lane & 3) * 2;
            float b0 = bias[col], b1 = bias[col + 1];
            #pragma unroll
            for (int half = 0; half < 2; half++) {
                int m = m0 + wm + i * 16 + (lane >> 2) + half * 8;
                float v0 = acc[i][j][half * 2 + 0] + b0;
                float v1 = acc[i][j][half * 2 + 1] + b1;
                if (z < 2) {
                    __nv_bfloat16 h0 = __float2bfloat16(v0);
                    __nv_bfloat16 h1 = __float2bfloat16(v1);
                    __nv_bfloat16 l0 = __float2bfloat16(v0 - __bfloat162float(h0));
                    __nv_bfloat16 l1 = __float2bfloat16(v1 - __bfloat162float(h1));
                    __nv_bfloat16* oh = (z == 0) ? gq_hi : gk_hi;
                    __nv_bfloat16* ol = (z == 0) ? gq_lo : gk_lo;
                    uint32_t ph, pl;
                    {
                        uint16_t a16 = __bfloat16_as_ushort(h0), b16 = __bfloat16_as_ushort(h1);
                        ph = (uint32_t)a16 | ((uint32_t)b16 << 16);
                        a16 = __bfloat16_as_ushort(l0); b16 = __bfloat16_as_ushort(l1);
                        pl = (uint32_t)a16 | ((uint32_t)b16 << 16);
                    }
                    *reinterpret_cast<uint32_t*>(oh + (size_t)m * DOUT + col) = ph;
                    *reinterpret_cast<uint32_t*>(ol + (size_t)m * DOUT + col) = pl;
                } else {
                    *reinterpret_cast<float2*>(gv_f + (size_t)m * DOUT + col) =
                        make_float2(v0, v1);
                }
            }
        }
    }
}

// ===========================================================================
// Kernel: scores = (Q.K^T)/32 + masks  (skips tiles above diagonal)
// ===========================================================================
__global__ __launch_bounds__(NTHREADS, 1) void scores_mma(const int* __restrict__ lengths)
{
    if (blockIdx.x > blockIdx.y) return;
    extern __shared__ char smem[];
    const uint32_t sb = smem_u32(smem);
    const int tid = threadIdx.x, wid = tid >> 5, lane = tid & 31;
    const int b = blockIdx.z;
    const int m0 = blockIdx.y * 128;
    const int n0 = blockIdx.x * 128;

    const __nv_bfloat16* aHi = gq_hi + ((size_t)b * SEQ + m0) * DOUT;
    const __nv_bfloat16* aLo = gq_lo + ((size_t)b * SEQ + m0) * DOUT;
    const __nv_bfloat16* bHi = gk_hi + ((size_t)b * SEQ + n0) * DOUT;
    const __nv_bfloat16* bLo = gk_lo + ((size_t)b * SEQ + n0) * DOUT;

    float acc[2][4][4];
    #pragma unroll
    for (int i = 0; i < 2; i++)
        #pragma unroll
        for (int j = 0; j < 4; j++)
            #pragma unroll
            for (int v = 0; v < 4; v++) acc[i][j][v] = 0.0f;

    gemm_mainloop(sb, DOUT / 64, aHi, aLo, DOUT, bHi, bLo, DOUT, acc, tid, wid, lane);

    const int len = lengths[b];
    const int wm = (wid & 3) * 32, wn = (wid >> 2) * 32;
    float* prow = gs_f + (size_t)b * SEQ * SEQ;
    #pragma unroll
    for (int i = 0; i < 2; i++) {
        #pragma unroll
        for (int j = 0; j < 4; j++) {
            int gj = n0 + wn + j * 8 + (lane & 3) * 2;
            #pragma unroll
            for (int half = 0; half < 2; half++) {
                int gi = m0 + wm + i * 16 + (lane >> 2) + half * 8;
                float s0 = acc[i][j][half * 2 + 0] * 0.03125f;
                float s1 = acc[i][j][half * 2 + 1] * 0.03125f;
                bool rowbad = (gi >= len);
                if (gj > gi)                 s0 += NEGC;
                if (rowbad || gj >= len)     s0 += NEGC;
                if (gj + 1 > gi)             s1 += NEGC;
                if (rowbad || gj + 1 >= len) s1 += NEGC;
                *reinterpret_cast<float2*>(prow + (size_t)gi * SEQ + gj) =
                    make_float2(s0, s1);
            }
        }
    }
}

// ===========================================================================
// Kernel: row softmax. Row cached in smem; exp computed once; __expf.
// Emits P as bf16 hi/lo (zeros past diagonal up to tile boundary).
// ===========================================================================
__global__ __launch_bounds__(256) void softmax_kernel()
{
    const int i = blockIdx.x;
    const int b = blockIdx.y;
    const float* row = gs_f + ((size_t)b * SEQ + i) * SEQ;
    const int n = i + 1;
    const int nr = ((i >> 7) + 1) << 7;
    __shared__ float buf[SEQ];
    __shared__ float red[8];
    const int tid = threadIdx.x, lane = tid & 31, wrp = tid >> 5;

    float m = -3.4e38f;
    for (int j = tid; j < n; j += 256) {
        float v = row[j];
        buf[j] = v;
        m = fmaxf(m, v);
    }
    #pragma unroll
    for (int o = 16; o; o >>= 1) m = fmaxf(m, __shfl_xor_sync(0xFFFFFFFFu, m, o));
    if (lane == 0) red[wrp] = m;
    __syncthreads();
    if (wrp == 0) {
        float t = red[lane & 7];
        #pragma unroll
        for (int o = 4; o; o >>= 1) t = fmaxf(t, __shfl_xor_sync(0xFFFFFFFFu, t, o));
        if (lane == 0) red[0] = t;
    }
    __syncthreads();
    m = red[0];

    float s = 0.0f;
    for (int j = tid; j < n; j += 256) {
        float e = __expf(buf[j] - m);
        buf[j] = e;
        s += e;
    }
    #pragma unroll
    for (int o = 16; o; o >>= 1) s += __shfl_xor_sync(0xFFFFFFFFu, s, o);
    __syncthreads();
    if (lane == 0) red[wrp] = s;
    __syncthreads();
    if (wrp == 0) {
        float t = red[lane & 7];
        #pragma unroll
        for (int o = 4; o; o >>= 1) t += __shfl_xor_sync(0xFFFFFFFFu, t, o);
        if (lane == 0) red[0] = t;
    }
    __syncthreads();
    const float r = 1.0f / red[0];

    size_t gbase = ((size_t)b * SEQ + i) * SEQ;
    for (int j = tid; j < nr; j += 256) {
        float p = (j < n) ? buf[j] * r : 0.0f;
        __nv_bfloat16 h = __float2bfloat16(p);
        gp_hi[gbase + j] = h;
        gp_lo[gbase + j] = __float2bfloat16(p - __bfloat162float(h));
    }
}

// ===========================================================================
// Kernel: transpose + split V -> Vt (K-major B operand for PV)
// ===========================================================================
__global__ __launch_bounds__(256) void vsplit_kernel()
{
    __shared__ float t[32][33];
    int b = blockIdx.z;
    int n0 = blockIdx.y * 32;
    int j0 = blockIdx.x * 32;
    int tx = threadIdx.x, ty = threadIdx.y;     // (32, 8)
    #pragma unroll
    for (int r = 0; r < 4; r++)
        t[ty + 8 * r][tx] = gv_f[((size_t)b * SEQ + j0 + ty + 8 * r) * DOUT + n0 + tx];
    __syncthreads();
    #pragma unroll
    for (int r = 0; r < 4; r++) {
        int nl = ty + 8 * r;
        float f = t[tx][nl];
        __nv_bfloat16 h = __float2bfloat16(f);
        size_t o = ((size_t)b * DOUT + n0 + nl) * SEQ + j0 + tx;
        gvt_hi[o] = h;
        gvt_lo[o] = __float2bfloat16(f - __bfloat162float(h));
    }
}

// ===========================================================================
// Kernel: O = P @ V  (K bounded by causal extent of the row tile)
// ===========================================================================
__global__ __launch_bounds__(NTHREADS, 1) void pv_mma(float* __restrict__ out)
{
    extern __shared__ char smem[];
    const uint32_t sb = smem_u32(smem);
    const int tid = threadIdx.x, wid = tid >> 5, lane = tid & 31;
    const int b = blockIdx.z;
    const int itile = blockIdx.y;
    const int m0 = itile * 128;
    const int n0 = blockIdx.x * 128;

    const __nv_bfloat16* aHi = gp_hi + ((size_t)b * SEQ + m0) * SEQ;
    const __nv_bfloat16* aLo = gp_lo + ((size_t)b * SEQ + m0) * SEQ;
    const __nv_bfloat16* bHi = gvt_hi + ((size_t)b * DOUT + n0) * SEQ;
    const __nv_bfloat16* bLo = gvt_lo + ((size_t)b * DOUT + n0) * SEQ;

    float acc[2][4][4];
    #pragma unroll
    for (int i = 0; i < 2; i++)
        #pragma unroll
        for (int j = 0; j < 4; j++)
            #pragma unroll
            for (int v = 0; v < 4; v++) acc[i][j][v] = 0.0f;

    gemm_mainloop(sb, (itile + 1) * 2, aHi, aLo, SEQ, bHi, bLo, SEQ, acc, tid, wid, lane);

    const int wm = (wid & 3) * 32, wn = (wid >> 2) * 32;
    #pragma unroll
    for (int i = 0; i < 2; i++) {
        #pragma unroll
        for (int j = 0; j < 4; j++) {
            int col = n0 + wn + j * 8 + (lane & 3) * 2;
            #pragma unroll
            for (int half = 0; half < 2; half++) {
                int m = m0 + wm + i * 16 + (lane >> 2) + half * 8;
                *reinterpret_cast<float2*>(out + ((size_t)b * SEQ + m) * DOUT + col) =
                    make_float2(acc[i][j][half * 2 + 0], acc[i][j][half * 2 + 1]);
            }
        }
    }
}

// ===========================================================================
extern "C" void kernel_launch(void* const* d_in, const int* in_sizes, int n_in,
                              void* d_out, int out_size)
{
    const float* x  = (const float*)d_in[0];
    const float* Wq = (const float*)d_in[1];
    const float* bq = (const float*)d_in[2];
    const float* Wk = (const float*)d_in[3];
    const float* bk = (const float*)d_in[4];
    const float* Wv = (const float*)d_in[5];
    const float* bv = (const float*)d_in[6];
    const int* lengths = (const int*)d_in[7];
    float* out = (float*)d_out;

    static bool attrs_set = false;
    if (!attrs_set) {
        cudaFuncSetAttribute(qkv_mma,    cudaFuncAttributeMaxDynamicSharedMemorySize, SMEM_BYTES);
        cudaFuncSetAttribute(scores_mma, cudaFuncAttributeMaxDynamicSharedMemorySize, SMEM_BYTES);
        cudaFuncSetAttribute(pv_mma,     cudaFuncAttributeMaxDynamicSharedMemorySize, SMEM_BYTES);
        attrs_set = true;
    }

    const int ntot = MTOT * DIN + 3 * DOUT * DIN;        // 11534336, /256 exact
    split_all_kernel<<<ntot / 256, 256>>>(x, Wq, Wk, Wv);

    dim3 g1(DOUT / 128, MTOT / 128, 3);                  // (8, 64, 3)
    qkv_mma<<<g1, NTHREADS, SMEM_BYTES>>>(bq, bk, bv);

    vsplit_kernel<<<dim3(SEQ / 32, DOUT / 32, BATCH), dim3(32, 8)>>>();

    dim3 g2(SEQ / 128, SEQ / 128, BATCH);                // (16, 16, 4)
    scores_mma<<<g2, NTHREADS, SMEM_BYTES>>>(lengths);

    softmax_kernel<<<dim3(SEQ, BATCH), 256>>>();

    dim3 g4(DOUT / 128, SEQ / 128, BATCH);               // (8, 16, 4)
    pv_mma<<<g4, NTHREADS, SMEM_BYTES>>>(out);
}

// round 11
// speedup vs baseline: 1.0430x; 1.0430x over previous
#include <cuda_runtime.h>
#include <cuda_bf16.h>
#include <cstdint>

#define BATCH 4
#define SEQ   2048
#define DIN   1024
#define DOUT  1024
#define MTOT  (BATCH * SEQ)
#define NEGC  (-1000000000.0f)

// ===========================================================================
// Scratch (device globals — allocations are forbidden)
// ===========================================================================
__device__ __nv_bfloat16 gx_hi[(size_t)MTOT * DIN];
__device__ __nv_bfloat16 gx_lo[(size_t)MTOT * DIN];
__device__ __nv_bfloat16 gw_hi[(size_t)3 * DOUT * DIN];
__device__ __nv_bfloat16 gw_lo[(size_t)3 * DOUT * DIN];
__device__ __nv_bfloat16 gq_hi[(size_t)MTOT * DOUT];
__device__ __nv_bfloat16 gq_lo[(size_t)MTOT * DOUT];
__device__ __nv_bfloat16 gk_hi[(size_t)MTOT * DOUT];
__device__ __nv_bfloat16 gk_lo[(size_t)MTOT * DOUT];
__device__ float         gv_f [(size_t)MTOT * DOUT];
__device__ __nv_bfloat16 gvt_hi[(size_t)BATCH * DOUT * SEQ];
__device__ __nv_bfloat16 gvt_lo[(size_t)BATCH * DOUT * SEQ];
__device__ float         gs_f [(size_t)BATCH * SEQ * SEQ];
__device__ __nv_bfloat16 gp_hi[(size_t)BATCH * SEQ * SEQ];
__device__ __nv_bfloat16 gp_lo[(size_t)BATCH * SEQ * SEQ];

// ===========================================================================
// Base-target PTX helpers (NO tcgen05 — harness compiles for sm_103 base)
// ===========================================================================
__device__ __forceinline__ uint32_t smem_u32(const void* p) {
    uint32_t a;
    asm("{ .reg .u64 t; cvta.to.shared.u64 t, %1; cvt.u32.u64 %0, t; }"
        : "=r"(a) : "l"(p));
    return a;
}

#define CP_ASYNC16(dst, src) \
    asm volatile("cp.async.cg.shared.global [%0], [%1], 16;" \
        :: "r"(dst), "l"(src))
#define CP_COMMIT()  asm volatile("cp.async.commit_group;" ::: "memory")
#define CP_WAIT(N)   asm volatile("cp.async.wait_group %0;" :: "n"(N) : "memory")

__device__ __forceinline__ void ldsm4(uint32_t* r, uint32_t addr) {
    asm volatile("ldmatrix.sync.aligned.m8n8.x4.shared.b16 {%0,%1,%2,%3}, [%4];"
        : "=r"(r[0]), "=r"(r[1]), "=r"(r[2]), "=r"(r[3]) : "r"(addr));
}

__device__ __forceinline__ void mma_bf16(float* c, const uint32_t* a, const uint32_t* b) {
    asm volatile(
        "mma.sync.aligned.m16n8k16.row.col.f32.bf16.bf16.f32 "
        "{%0,%1,%2,%3}, {%4,%5,%6,%7}, {%8,%9}, {%0,%1,%2,%3};"
        : "+f"(c[0]), "+f"(c[1]), "+f"(c[2]), "+f"(c[3])
        : "r"(a[0]), "r"(a[1]), "r"(a[2]), "r"(a[3]), "r"(b[0]), "r"(b[1]));
}

// ===========================================================================
// Shared GEMM engine: 128x128 CTA tile, 8 warps (2m x 4n, 64x32 warp tile),
// BK=64, 3-stage cp.async pipeline, SW128 XOR swizzle, bf16x3 split precision,
// double-buffered fragment prefetch across k16 steps.
// SMEM per stage: A_hi | A_lo | B_hi | B_lo, each 128 rows x 128B = 16KB.
// ===========================================================================
#define NTHREADS    256
#define SUB_BYTES   16384
#define STAGE_BYTES 65536
#define NSTAGE      3
#define SMEM_BYTES  (NSTAGE * STAGE_BYTES)    // 196608

__device__ __forceinline__ void fill_stage(
    uint32_t sb, int stage,
    const __nv_bfloat16* aHi, const __nv_bfloat16* aLo, size_t strideA,
    const __nv_bfloat16* bHi, const __nv_bfloat16* bLo, size_t strideB,
    int k0, int tid)
{
    uint32_t base = sb + stage * STAGE_BYTES;
    #pragma unroll
    for (int sub = 0; sub < 4; sub++) {
        const __nv_bfloat16* src = (sub == 0) ? aHi : (sub == 1) ? aLo
                                 : (sub == 2) ? bHi : bLo;
        size_t stride = (sub < 2) ? strideA : strideB;
        uint32_t dst = base + sub * SUB_BYTES;
        #pragma unroll
        for (int t = 0; t < 4; t++) {
            int idx = tid + NTHREADS * t;        // [0,1024)
            int r = idx >> 3;                    // row 0..127
            int c = idx & 7;                     // 16B chunk 0..7
            uint32_t d = dst + (uint32_t)(r * 128 + ((c ^ (r & 7)) << 4));
            const void* g = src + (size_t)r * stride + k0 + c * 8;
            CP_ASYNC16(d, g);
        }
    }
    CP_COMMIT();
}

// Load all fragments for one k16 step into the given register buffers.
__device__ __forceinline__ void load_frags(
    uint32_t base, int ks, int wm, int wn, int lane,
    uint32_t aH[4][4], uint32_t aL[4][4], uint32_t bH[4][2], uint32_t bL[4][2])
{
    #pragma unroll
    for (int i = 0; i < 4; i++) {
        int row = wm + i * 16 + (lane & 15);
        int cb  = ks * 2 + (lane >> 4);
        uint32_t ad = base + (uint32_t)(row * 128 + ((cb ^ (row & 7)) << 4));
        ldsm4(aH[i], ad);
        ldsm4(aL[i], ad + SUB_BYTES);
    }
    #pragma unroll
    for (int jp = 0; jp < 2; jp++) {
        int g   = lane >> 3;                             // 0..3
        int row = wn + (jp * 2 + (g >> 1)) * 8 + (lane & 7);
        int cb  = ks * 2 + (g & 1);
        uint32_t bd = base + 2 * SUB_BYTES
                    + (uint32_t)(row * 128 + ((cb ^ (row & 7)) << 4));
        uint32_t t[4];
        ldsm4(t, bd);
        bH[jp*2][0] = t[0]; bH[jp*2][1] = t[1];
        bH[jp*2+1][0] = t[2]; bH[jp*2+1][1] = t[3];
        ldsm4(t, bd + SUB_BYTES);
        bL[jp*2][0] = t[0]; bL[jp*2][1] = t[1];
        bL[jp*2+1][0] = t[2]; bL[jp*2+1][1] = t[3];
    }
}

// Compute one stage (4 k16-steps, 3 split passes) into acc[4][4][4] with
// double-buffered fragment prefetch: LDSM for ks+1 issue before HMMAs of ks,
// hiding LDS latency behind ~36 tensor instructions.
__device__ __forceinline__ void compute_stage(
    uint32_t sb, int stage, float acc[4][4][4], int wid, int lane)
{
    uint32_t base = sb + stage * STAGE_BYTES;
    const int wm = (wid & 1) * 64;
    const int wn = (wid >> 1) * 32;

    uint32_t aH[2][4][4], aL[2][4][4], bH[2][4][2], bL[2][4][2];
    load_frags(base, 0, wm, wn, lane, aH[0], aL[0], bH[0], bL[0]);

    #pragma unroll
    for (int ks = 0; ks < 4; ks++) {
        const int cur = ks & 1, nxt = cur ^ 1;
        if (ks < 3)
            load_frags(base, ks + 1, wm, wn, lane, aH[nxt], aL[nxt], bH[nxt], bL[nxt]);
        #pragma unroll
        for (int i = 0; i < 4; i++)
            #pragma unroll
            for (int j = 0; j < 4; j++) {
                mma_bf16(acc[i][j], aH[cur][i], bH[cur][j]);
                mma_bf16(acc[i][j], aH[cur][i], bL[cur][j]);
                mma_bf16(acc[i][j], aL[cur][i], bH[cur][j]);
            }
    }
}

// Full K loop, 3-stage pipeline, one barrier per iteration.
__device__ __forceinline__ void gemm_mainloop(
    uint32_t sb, int nch,
    const __nv_bfloat16* aHi, const __nv_bfloat16* aLo, size_t strideA,
    const __nv_bfloat16* bHi, const __nv_bfloat16* bLo, size_t strideB,
    float acc[4][4][4], int tid, int wid, int lane)
{
    fill_stage(sb, 0, aHi, aLo, strideA, bHi, bLo, strideB, 0, tid);
    if (nch > 1)
        fill_stage(sb, 1, aHi, aLo, strideA, bHi, bLo, strideB, 64, tid);

    int stage = 0;
    for (int ch = 0; ch < nch; ch++) {
        if (ch + 1 < nch) CP_WAIT(1); else CP_WAIT(0);
        __syncthreads();
        compute_stage(sb, stage, acc, wid, lane);
        int nf = ch + 2;
        if (nf < nch) {
            int fs = stage + 2; if (fs >= NSTAGE) fs -= NSTAGE;
            fill_stage(sb, fs, aHi, aLo, strideA, bHi, bLo, strideB, nf * 64, tid);
        }
        if (++stage == NSTAGE) stage = 0;
    }
}

// ===========================================================================
// Kernel: merged split fp32 -> bf16 (hi, lo) for x, Wq, Wk, Wv (one launch)
// ===========================================================================
__global__ __launch_bounds__(256) void split_all_kernel(
    const float* __restrict__ x,  const float* __restrict__ Wq,
    const float* __restrict__ Wk, const float* __restrict__ Wv)
{
    const int nx = MTOT * DIN;
    const int nw = DOUT * DIN;
    int i = blockIdx.x * 256 + threadIdx.x;
    const float* src; __nv_bfloat16 *hi, *lo; int idx;
    if (i < nx) {
        src = x; idx = i; hi = gx_hi; lo = gx_lo;
    } else {
        int t = i - nx;
        int z = t / nw;
        idx = t - z * nw;
        src = (z == 0) ? Wq : (z == 1) ? Wk : Wv;
        hi = gw_hi + (size_t)z * nw;
        lo = gw_lo + (size_t)z * nw;
    }
    float f = src[idx];
    __nv_bfloat16 h = __float2bfloat16(f);
    hi[idx] = h;
    lo[idx] = __float2bfloat16(f - __bfloat162float(h));
}

// ===========================================================================
// Kernel: QKV projection.  z selects Q/K/V.
// ===========================================================================
__global__ __launch_bounds__(NTHREADS, 1) void qkv_mma(
    const float* __restrict__ bq, const float* __restrict__ bk,
    const float* __restrict__ bv)
{
    extern __shared__ char smem[];
    const uint32_t sb = smem_u32(smem);
    const int tid = threadIdx.x, wid = tid >> 5, lane = tid & 31;
    const int z = blockIdx.z;
    const int m0 = blockIdx.y * 128;
    const int n0 = blockIdx.x * 128;

    const __nv_bfloat16* aHi = gx_hi + (size_t)m0 * DIN;
    const __nv_bfloat16* aLo = gx_lo + (size_t)m0 * DIN;
    size_t woff = (size_t)z * DOUT * DIN + (size_t)n0 * DIN;
    const __nv_bfloat16* bHi = gw_hi + woff;
    const __nv_bfloat16* bLo = gw_lo + woff;
    const float* bias = (z == 0) ? bq : (z == 1) ? bk : bv;

    float acc[4][4][4];
    #pragma unroll
    for (int i = 0; i < 4; i++)
        #pragma unroll
        for (int j = 0; j < 4; j++)
            #pragma unroll
            for (int v = 0; v < 4; v++) acc[i][j][v] = 0.0f;

    gemm_mainloop(sb, DIN / 64, aHi, aLo, DIN, bHi, bLo, DIN, acc, tid, wid, lane);

    const int wm = (wid & 1) * 64, wn = (wid >> 1) * 32;
    #pragma unroll
    for (int i = 0; i < 4; i++) {
        #pragma unroll
        for (int j = 0; j < 4; j++) {
            int col = n0 + wn + j * 8 + (lane & 3) * 2;
            float b0 = bias[col], b1 = bias[col + 1];
            #pragma unroll
            for (int half = 0; half < 2; half++) {
                int m = m0 + wm + i * 16 + (lane >> 2) + half * 8;
                float v0 = acc[i][j][half * 2 + 0] + b0;
                float v1 = acc[i][j][half * 2 + 1] + b1;
                if (z < 2) {
                    __nv_bfloat16 h0 = __float2bfloat16(v0);
                    __nv_bfloat16 h1 = __float2bfloat16(v1);
                    __nv_bfloat16 l0 = __float2bfloat16(v0 - __bfloat162float(h0));
                    __nv_bfloat16 l1 = __float2bfloat16(v1 - __bfloat162float(h1));
                    __nv_bfloat16* oh = (z == 0) ? gq_hi : gk_hi;
                    __nv_bfloat16* ol = (z == 0) ? gq_lo : gk_lo;
                    uint32_t ph, pl;
                    {
                        uint16_t a16 = __bfloat16_as_ushort(h0), b16 = __bfloat16_as_ushort(h1);
                        ph = (uint32_t)a16 | ((uint32_t)b16 << 16);
                        a16 = __bfloat16_as_ushort(l0); b16 = __bfloat16_as_ushort(l1);
                        pl = (uint32_t)a16 | ((uint32_t)b16 << 16);
                    }
                    *reinterpret_cast<uint32_t*>(oh + (size_t)m * DOUT + col) = ph;
                    *reinterpret_cast<uint32_t*>(ol + (size_t)m * DOUT + col) = pl;
                } else {
                    *reinterpret_cast<float2*>(gv_f + (size_t)m * DOUT + col) =
                        make_float2(v0, v1);
                }
            }
        }
    }
}

// ===========================================================================
// Kernel: scores = (Q.K^T)/32 + masks  (skips tiles above diagonal)
// ===========================================================================
__global__ __launch_bounds__(NTHREADS, 1) void scores_mma(const int* __restrict__ lengths)
{
    if (blockIdx.x > blockIdx.y) return;
    extern __shared__ char smem[];
    const uint32_t sb = smem_u32(smem);
    const int tid = threadIdx.x, wid = tid >> 5, lane = tid & 31;
    const int b = blockIdx.z;
    const int m0 = blockIdx.y * 128;
    const int n0 = blockIdx.x * 128;

    const __nv_bfloat16* aHi = gq_hi + ((size_t)b * SEQ + m0) * DOUT;
    const __nv_bfloat16* aLo = gq_lo + ((size_t)b * SEQ + m0) * DOUT;
    const __nv_bfloat16* bHi = gk_hi + ((size_t)b * SEQ + n0) * DOUT;
    const __nv_bfloat16* bLo = gk_lo + ((size_t)b * SEQ + n0) * DOUT;

    float acc[4][4][4];
    #pragma unroll
    for (int i = 0; i < 4; i++)
        #pragma unroll
        for (int j = 0; j < 4; j++)
            #pragma unroll
            for (int v = 0; v < 4; v++) acc[i][j][v] = 0.0f;

    gemm_mainloop(sb, DOUT / 64, aHi, aLo, DOUT, bHi, bLo, DOUT, acc, tid, wid, lane);

    const int len = lengths[b];
    const int wm = (wid & 1) * 64, wn = (wid >> 1) * 32;
    float* prow = gs_f + (size_t)b * SEQ * SEQ;
    #pragma unroll
    for (int i = 0; i < 4; i++) {
        #pragma unroll
        for (int j = 0; j < 4; j++) {
            int gj = n0 + wn + j * 8 + (lane & 3) * 2;
            #pragma unroll
            for (int half = 0; half < 2; half++) {
                int gi = m0 + wm + i * 16 + (lane >> 2) + half * 8;
                float s0 = acc[i][j][half * 2 + 0] * 0.03125f;
                float s1 = acc[i][j][half * 2 + 1] * 0.03125f;
                bool rowbad = (gi >= len);
                if (gj > gi)                 s0 += NEGC;
                if (rowbad || gj >= len)     s0 += NEGC;
                if (gj + 1 > gi)             s1 += NEGC;
                if (rowbad || gj + 1 >= len) s1 += NEGC;
                *reinterpret_cast<float2*>(prow + (size_t)gi * SEQ + gj) =
                    make_float2(s0, s1);
            }
        }
    }
}

// ===========================================================================
// Kernel: row softmax. Row cached in smem; exp computed once; __expf.
// Emits P as bf16 hi/lo (zeros past diagonal up to tile boundary).
// ===========================================================================
__global__ __launch_bounds__(256) void softmax_kernel()
{
    const int i = blockIdx.x;
    const int b = blockIdx.y;
    const float* row = gs_f + ((size_t)b * SEQ + i) * SEQ;
    const int n = i + 1;
    const int nr = ((i >> 7) + 1) << 7;
    __shared__ float buf[SEQ];
    __shared__ float red[8];
    const int tid = threadIdx.x, lane = tid & 31, wrp = tid >> 5;

    float m = -3.4e38f;
    for (int j = tid; j < n; j += 256) {
        float v = row[j];
        buf[j] = v;
        m = fmaxf(m, v);
    }
    #pragma unroll
    for (int o = 16; o; o >>= 1) m = fmaxf(m, __shfl_xor_sync(0xFFFFFFFFu, m, o));
    if (lane == 0) red[wrp] = m;
    __syncthreads();
    if (wrp == 0) {
        float t = red[lane & 7];
        #pragma unroll
        for (int o = 4; o; o >>= 1) t = fmaxf(t, __shfl_xor_sync(0xFFFFFFFFu, t, o));
        if (lane == 0) red[0] = t;
    }
    __syncthreads();
    m = red[0];

    float s = 0.0f;
    for (int j = tid; j < n; j += 256) {
        float e = __expf(buf[j] - m);
        buf[j] = e;
        s += e;
    }
    #pragma unroll
    for (int o = 16; o; o >>= 1) s += __shfl_xor_sync(0xFFFFFFFFu, s, o);
    __syncthreads();
    if (lane == 0) red[wrp] = s;
    __syncthreads();
    if (wrp == 0) {
        float t = red[lane & 7];
        #pragma unroll
        for (int o = 4; o; o >>= 1) t += __shfl_xor_sync(0xFFFFFFFFu, t, o);
        if (lane == 0) red[0] = t;
    }
    __syncthreads();
    const float r = 1.0f / red[0];

    size_t gbase = ((size_t)b * SEQ + i) * SEQ;
    for (int j = tid; j < nr; j += 256) {
        float p = (j < n) ? buf[j] * r : 0.0f;
        __nv_bfloat16 h = __float2bfloat16(p);
        gp_hi[gbase + j] = h;
        gp_lo[gbase + j] = __float2bfloat16(p - __bfloat162float(h));
    }
}

// ===========================================================================
// Kernel: transpose + split V -> Vt (K-major B operand for PV)
// ===========================================================================
__global__ __launch_bounds__(256) void vsplit_kernel()
{
    __shared__ float t[32][33];
    int b = blockIdx.z;
    int n0 = blockIdx.y * 32;
    int j0 = blockIdx.x * 32;
    int tx = threadIdx.x, ty = threadIdx.y;     // (32, 8)
    #pragma unroll
    for (int r = 0; r < 4; r++)
        t[ty + 8 * r][tx] = gv_f[((size_t)b * SEQ + j0 + ty + 8 * r) * DOUT + n0 + tx];
    __syncthreads();
    #pragma unroll
    for (int r = 0; r < 4; r++) {
        int nl = ty + 8 * r;
        float f = t[tx][nl];
        __nv_bfloat16 h = __float2bfloat16(f);
        size_t o = ((size_t)b * DOUT + n0 + nl) * SEQ + j0 + tx;
        gvt_hi[o] = h;
        gvt_lo[o] = __float2bfloat16(f - __bfloat162float(h));
    }
}

// ===========================================================================
// Kernel: O = P @ V  (K bounded by causal extent of the row tile)
// ===========================================================================
__global__ __launch_bounds__(NTHREADS, 1) void pv_mma(float* __restrict__ out)
{
    extern __shared__ char smem[];
    const uint32_t sb = smem_u32(smem);
    const int tid = threadIdx.x, wid = tid >> 5, lane = tid & 31;
    const int b = blockIdx.z;
    const int itile = blockIdx.y;
    const int m0 = itile * 128;
    const int n0 = blockIdx.x * 128;

    const __nv_bfloat16* aHi = gp_hi + ((size_t)b * SEQ + m0) * SEQ;
    const __nv_bfloat16* aLo = gp_lo + ((size_t)b * SEQ + m0) * SEQ;
    const __nv_bfloat16* bHi = gvt_hi + ((size_t)b * DOUT + n0) * SEQ;
    const __nv_bfloat16* bLo = gvt_lo + ((size_t)b * DOUT + n0) * SEQ;

    float acc[4][4][4];
    #pragma unroll
    for (int i = 0; i < 4; i++)
        #pragma unroll
        for (int j = 0; j < 4; j++)
            #pragma unroll
            for (int v = 0; v < 4; v++) acc[i][j][v] = 0.0f;

    gemm_mainloop(sb, (itile + 1) * 2, aHi, aLo, SEQ, bHi, bLo, SEQ, acc, tid, wid, lane);

    const int wm = (wid & 1) * 64, wn = (wid >> 1) * 32;
    #pragma unroll
    for (int i = 0; i < 4; i++) {
        #pragma unroll
        for (int j = 0; j < 4; j++) {
            int col = n0 + wn + j * 8 + (lane & 3) * 2;
            #pragma unroll
            for (int half = 0; half < 2; half++) {
                int m = m0 + wm + i * 16 + (lane >> 2) + half * 8;
                *reinterpret_cast<float2*>(out + ((size_t)b * SEQ + m) * DOUT + col) =
                    make_float2(acc[i][j][half * 2 + 0], acc[i][j][half * 2 + 1]);
            }
        }
    }
}

// ===========================================================================
extern "C" void kernel_launch(void* const* d_in, const int* in_sizes, int n_in,
                              void* d_out, int out_size)
{
    const float* x  = (const float*)d_in[0];
    const float* Wq = (const float*)d_in[1];
    const float* bq = (const float*)d_in[2];
    const float* Wk = (const float*)d_in[3];
    const float* bk = (const float*)d_in[4];
    const float* Wv = (const float*)d_in[5];
    const float* bv = (const float*)d_in[6];
    const int* lengths = (const int*)d_in[7];
    float* out = (float*)d_out;

    static bool attrs_set = false;
    if (!attrs_set) {
        cudaFuncSetAttribute(qkv_mma,    cudaFuncAttributeMaxDynamicSharedMemorySize, SMEM_BYTES);
        cudaFuncSetAttribute(scores_mma, cudaFuncAttributeMaxDynamicSharedMemorySize, SMEM_BYTES);
        cudaFuncSetAttribute(pv_mma,     cudaFuncAttributeMaxDynamicSharedMemorySize, SMEM_BYTES);
        attrs_set = true;
    }

    const int ntot = MTOT * DIN + 3 * DOUT * DIN;        // 11534336, /256 exact
    split_all_kernel<<<ntot / 256, 256>>>(x, Wq, Wk, Wv);

    dim3 g1(DOUT / 128, MTOT / 128, 3);                  // (8, 64, 3)
    qkv_mma<<<g1, NTHREADS, SMEM_BYTES>>>(bq, bk, bv);

    vsplit_kernel<<<dim3(SEQ / 32, DOUT / 32, BATCH), dim3(32, 8)>>>();

    dim3 g2(SEQ / 128, SEQ / 128, BATCH);                // (16, 16, 4)
    scores_mma<<<g2, NTHREADS, SMEM_BYTES>>>(lengths);

    softmax_kernel<<<dim3(SEQ, BATCH), 256>>>();

    dim3 g4(DOUT / 128, SEQ / 128, BATCH);               // (8, 16, 4)
    pv_mma<<<g4, NTHREADS, SMEM_BYTES>>>(out);
}

// round 12
// speedup vs baseline: 1.0641x; 1.0203x over previous
#include <cuda_runtime.h>
#include <cuda_bf16.h>
#include <cstdint>

#define BATCH 4
#define SEQ   2048
#define DIN   1024
#define DOUT  1024
#define MTOT  (BATCH * SEQ)
#define NEGC  (-1000000000.0f)

// ===========================================================================
// Scratch (device globals — allocations are forbidden)
// ===========================================================================
__device__ __nv_bfloat16 gx_hi[(size_t)MTOT * DIN];
__device__ __nv_bfloat16 gx_lo[(size_t)MTOT * DIN];
__device__ __nv_bfloat16 gw_hi[(size_t)3 * DOUT * DIN];
__device__ __nv_bfloat16 gw_lo[(size_t)3 * DOUT * DIN];
__device__ __nv_bfloat16 gq_hi[(size_t)MTOT * DOUT];
__device__ __nv_bfloat16 gq_lo[(size_t)MTOT * DOUT];
__device__ __nv_bfloat16 gk_hi[(size_t)MTOT * DOUT];
__device__ __nv_bfloat16 gk_lo[(size_t)MTOT * DOUT];
__device__ float         gv_f [(size_t)MTOT * DOUT];
__device__ __nv_bfloat16 gvt_hi[(size_t)BATCH * DOUT * SEQ];
__device__ __nv_bfloat16 gvt_lo[(size_t)BATCH * DOUT * SEQ];
__device__ float         gs_f [(size_t)BATCH * SEQ * SEQ];
__device__ __nv_bfloat16 gp_hi[(size_t)BATCH * SEQ * SEQ];
__device__ __nv_bfloat16 gp_lo[(size_t)BATCH * SEQ * SEQ];

// ===========================================================================
// Base-target PTX helpers (NO tcgen05 — harness compiles for sm_103 base)
// ===========================================================================
__device__ __forceinline__ uint32_t smem_u32(const void* p) {
    uint32_t a;
    asm("{ .reg .u64 t; cvta.to.shared.u64 t, %1; cvt.u32.u64 %0, t; }"
        : "=r"(a) : "l"(p));
    return a;
}

#define CP_ASYNC16(dst, src) \
    asm volatile("cp.async.cg.shared.global [%0], [%1], 16;" \
        :: "r"(dst), "l"(src))
#define CP_COMMIT()  asm volatile("cp.async.commit_group;" ::: "memory")
#define CP_WAIT(N)   asm volatile("cp.async.wait_group %0;" :: "n"(N) : "memory")

__device__ __forceinline__ void ldsm4(uint32_t* r, uint32_t addr) {
    asm volatile("ldmatrix.sync.aligned.m8n8.x4.shared.b16 {%0,%1,%2,%3}, [%4];"
        : "=r"(r[0]), "=r"(r[1]), "=r"(r[2]), "=r"(r[3]) : "r"(addr));
}

__device__ __forceinline__ void mma_bf16(float* c, const uint32_t* a, const uint32_t* b) {
    asm volatile(
        "mma.sync.aligned.m16n8k16.row.col.f32.bf16.bf16.f32 "
        "{%0,%1,%2,%3}, {%4,%5,%6,%7}, {%8,%9}, {%0,%1,%2,%3};"
        : "+f"(c[0]), "+f"(c[1]), "+f"(c[2]), "+f"(c[3])
        : "r"(a[0]), "r"(a[1]), "r"(a[2]), "r"(a[3]), "r"(b[0]), "r"(b[1]));
}

// ===========================================================================
// Shared GEMM engine: 128x64 CTA tile, 8 warps (4m x 2n, 32x32 warp tile),
// BK=64, 2-stage cp.async pipeline, SW128 XOR swizzle, bf16x3 split precision.
// Stage: A_hi(16K) | A_lo(16K) | B_hi(8K) | B_lo(8K) = 48KB; 2 stages = 96KB
// -> 2 CTAs/SM so prologue/epilogue/barrier tails overlap across CTAs.
// ===========================================================================
#define NTHREADS    256
#define A_SUB       16384
#define B_SUB       8192
#define STAGE_BYTES 49152
#define SMEM_BYTES  (2 * STAGE_BYTES)    // 98304
#define OFF_AHI     0
#define OFF_ALO     16384
#define OFF_BHI     32768
#define OFF_BLO     40960

__device__ __forceinline__ void fill_stage(
    uint32_t sb, int stage,
    const __nv_bfloat16* aHi, const __nv_bfloat16* aLo, size_t strideA,
    const __nv_bfloat16* bHi, const __nv_bfloat16* bLo, size_t strideB,
    int k0, int tid)
{
    uint32_t base = sb + stage * STAGE_BYTES;
    // A subs: 128 rows x 8 chunks = 1024 chunks each
    #pragma unroll
    for (int sub = 0; sub < 2; sub++) {
        const __nv_bfloat16* src = sub ? aLo : aHi;
        uint32_t dst = base + (sub ? OFF_ALO : OFF_AHI);
        #pragma unroll
        for (int t = 0; t < 4; t++) {
            int idx = tid + NTHREADS * t;        // [0,1024)
            int r = idx >> 3;
            int c = idx & 7;
            uint32_t d = dst + (uint32_t)(r * 128 + ((c ^ (r & 7)) << 4));
            CP_ASYNC16(d, src + (size_t)r * strideA + k0 + c * 8);
        }
    }
    // B subs: 64 rows x 8 chunks = 512 chunks each
    #pragma unroll
    for (int sub = 0; sub < 2; sub++) {
        const __nv_bfloat16* src = sub ? bLo : bHi;
        uint32_t dst = base + (sub ? OFF_BLO : OFF_BHI);
        #pragma unroll
        for (int t = 0; t < 2; t++) {
            int idx = tid + NTHREADS * t;        // [0,512)
            int r = idx >> 3;
            int c = idx & 7;
            uint32_t d = dst + (uint32_t)(r * 128 + ((c ^ (r & 7)) << 4));
            CP_ASYNC16(d, src + (size_t)r * strideB + k0 + c * 8);
        }
    }
    CP_COMMIT();
}

// Compute one stage (4 k16-steps, 3 split passes) into acc[2][4][4].
// Warp layout 4m x 2n; warp tile 32(m) x 32(n).
__device__ __forceinline__ void compute_stage(
    uint32_t sb, int stage, float acc[2][4][4], int wid, int lane)
{
    uint32_t base = sb + stage * STAGE_BYTES;
    const int wm = (wid & 3) * 32;
    const int wn = (wid >> 2) * 32;
    #pragma unroll
    for (int ks = 0; ks < 4; ks++) {
        uint32_t aH[2][4], aL[2][4], bH[4][2], bL[4][2];
        #pragma unroll
        for (int i = 0; i < 2; i++) {
            int row = wm + i * 16 + (lane & 15);
            int cb  = ks * 2 + (lane >> 4);
            uint32_t ad = base + (uint32_t)(row * 128 + ((cb ^ (row & 7)) << 4));
            ldsm4(aH[i], ad + OFF_AHI);
            ldsm4(aL[i], ad + OFF_ALO);
        }
        // B: two n-tiles per ldmatrix.x4 (lane groups of 8 pick tile/k-half)
        #pragma unroll
        for (int jp = 0; jp < 2; jp++) {
            int g   = lane >> 3;                         // 0..3
            int row = wn + (jp * 2 + (g >> 1)) * 8 + (lane & 7);
            int cb  = ks * 2 + (g & 1);
            uint32_t bd = base + (uint32_t)(row * 128 + ((cb ^ (row & 7)) << 4));
            uint32_t t[4];
            ldsm4(t, bd + OFF_BHI);
            bH[jp*2][0] = t[0]; bH[jp*2][1] = t[1];
            bH[jp*2+1][0] = t[2]; bH[jp*2+1][1] = t[3];
            ldsm4(t, bd + OFF_BLO);
            bL[jp*2][0] = t[0]; bL[jp*2][1] = t[1];
            bL[jp*2+1][0] = t[2]; bL[jp*2+1][1] = t[3];
        }
        #pragma unroll
        for (int i = 0; i < 2; i++)
            #pragma unroll
            for (int j = 0; j < 4; j++) {
                mma_bf16(acc[i][j], aH[i], bH[j]);
                mma_bf16(acc[i][j], aH[i], bL[j]);
                mma_bf16(acc[i][j], aL[i], bH[j]);
            }
    }
}

// 2-stage K loop; trailing sync makes the refill race-safe. The extra
// barrier overlaps with the co-resident CTA's compute (2 CTAs/SM).
__device__ __forceinline__ void gemm_mainloop(
    uint32_t sb, int nch,
    const __nv_bfloat16* aHi, const __nv_bfloat16* aLo, size_t strideA,
    const __nv_bfloat16* bHi, const __nv_bfloat16* bLo, size_t strideB,
    float acc[2][4][4], int tid, int wid, int lane)
{
    fill_stage(sb, 0, aHi, aLo, strideA, bHi, bLo, strideB, 0, tid);
    for (int ch = 0; ch < nch; ch++) {
        if (ch + 1 < nch) {
            fill_stage(sb, (ch + 1) & 1, aHi, aLo, strideA, bHi, bLo, strideB,
                       (ch + 1) * 64, tid);
            CP_WAIT(1);
        } else {
            CP_WAIT(0);
        }
        __syncthreads();
        compute_stage(sb, ch & 1, acc, wid, lane);
        __syncthreads();   // buffer (ch&1) free before next iteration's fill
    }
}

// ===========================================================================
// Kernel: merged split fp32 -> bf16 (hi, lo) for x, Wq, Wk, Wv (one launch)
// ===========================================================================
__global__ __launch_bounds__(256) void split_all_kernel(
    const float* __restrict__ x,  const float* __restrict__ Wq,
    const float* __restrict__ Wk, const float* __restrict__ Wv)
{
    const int nx = MTOT * DIN;
    const int nw = DOUT * DIN;
    int i = blockIdx.x * 256 + threadIdx.x;
    const float* src; __nv_bfloat16 *hi, *lo; int idx;
    if (i < nx) {
        src = x; idx = i; hi = gx_hi; lo = gx_lo;
    } else {
        int t = i - nx;
        int z = t / nw;
        idx = t - z * nw;
        src = (z == 0) ? Wq : (z == 1) ? Wk : Wv;
        hi = gw_hi + (size_t)z * nw;
        lo = gw_lo + (size_t)z * nw;
    }
    float f = src[idx];
    __nv_bfloat16 h = __float2bfloat16(f);
    hi[idx] = h;
    lo[idx] = __float2bfloat16(f - __bfloat162float(h));
}

// ===========================================================================
// Kernel: QKV projection.  z selects Q/K/V.  n-tile is 64 wide.
// ===========================================================================
__global__ __launch_bounds__(NTHREADS, 2) void qkv_mma(
    const float* __restrict__ bq, const float* __restrict__ bk,
    const float* __restrict__ bv)
{
    extern __shared__ char smem[];
    const uint32_t sb = smem_u32(smem);
    const int tid = threadIdx.x, wid = tid >> 5, lane = tid & 31;
    const int z = blockIdx.z;
    const int m0 = blockIdx.y * 128;
    const int n0 = blockIdx.x * 64;

    const __nv_bfloat16* aHi = gx_hi + (size_t)m0 * DIN;
    const __nv_bfloat16* aLo = gx_lo + (size_t)m0 * DIN;
    size_t woff = (size_t)z * DOUT * DIN + (size_t)n0 * DIN;
    const __nv_bfloat16* bHi = gw_hi + woff;
    const __nv_bfloat16* bLo = gw_lo + woff;
    const float* bias = (z == 0) ? bq : (z == 1) ? bk : bv;

    float acc[2][4][4];
    #pragma unroll
    for (int i = 0; i < 2; i++)
        #pragma unroll
        for (int j = 0; j < 4; j++)
            #pragma unroll
            for (int v = 0; v < 4; v++) acc[i][j][v] = 0.0f;

    gemm_mainloop(sb, DIN / 64, aHi, aLo, DIN, bHi, bLo, DIN, acc, tid, wid, lane);

    const int wm = (wid & 3) * 32, wn = (wid >> 2) * 32;
    #pragma unroll
    for (int i = 0; i < 2; i++) {
        #pragma unroll
        for (int j = 0; j < 4; j++) {
            int col = n0 + wn + j * 8 + (lane & 3) * 2;
            float b0 = bias[col], b1 = bias[col + 1];
            #pragma unroll
            for (int half = 0; half < 2; half++) {
                int m = m0 + wm + i * 16 + (lane >> 2) + half * 8;
                float v0 = acc[i][j][half * 2 + 0] + b0;
                float v1 = acc[i][j][half * 2 + 1] + b1;
                if (z < 2) {
                    __nv_bfloat16 h0 = __float2bfloat16(v0);
                    __nv_bfloat16 h1 = __float2bfloat16(v1);
                    __nv_bfloat16 l0 = __float2bfloat16(v0 - __bfloat162float(h0));
                    __nv_bfloat16 l1 = __float2bfloat16(v1 - __bfloat162float(h1));
                    __nv_bfloat16* oh = (z == 0) ? gq_hi : gk_hi;
                    __nv_bfloat16* ol = (z == 0) ? gq_lo : gk_lo;
                    uint32_t ph, pl;
                    {
                        uint16_t a16 = __bfloat16_as_ushort(h0), b16 = __bfloat16_as_ushort(h1);
                        ph = (uint32_t)a16 | ((uint32_t)b16 << 16);
                        a16 = __bfloat16_as_ushort(l0); b16 = __bfloat16_as_ushort(l1);
                        pl = (uint32_t)a16 | ((uint32_t)b16 << 16);
                    }
                    *reinterpret_cast<uint32_t*>(oh + (size_t)m * DOUT + col) = ph;
                    *reinterpret_cast<uint32_t*>(ol + (size_t)m * DOUT + col) = pl;
                } else {
                    *reinterpret_cast<float2*>(gv_f + (size_t)m * DOUT + col) =
                        make_float2(v0, v1);
                }
            }
        }
    }
}

// ===========================================================================
// Kernel: scores = (Q.K^T)/32 + masks  (skips tiles above diagonal)
// j-tile is 64 wide: skip when jtile*64 > itile*128 + 127.
// ===========================================================================
__global__ __launch_bounds__(NTHREADS, 2) void scores_mma(const int* __restrict__ lengths)
{
    const int m0 = blockIdx.y * 128;
    const int n0 = blockIdx.x * 64;
    if (n0 > m0 + 127) return;
    extern __shared__ char smem[];
    const uint32_t sb = smem_u32(smem);
    const int tid = threadIdx.x, wid = tid >> 5, lane = tid & 31;
    const int b = blockIdx.z;

    const __nv_bfloat16* aHi = gq_hi + ((size_t)b * SEQ + m0) * DOUT;
    const __nv_bfloat16* aLo = gq_lo + ((size_t)b * SEQ + m0) * DOUT;
    const __nv_bfloat16* bHi = gk_hi + ((size_t)b * SEQ + n0) * DOUT;
    const __nv_bfloat16* bLo = gk_lo + ((size_t)b * SEQ + n0) * DOUT;

    float acc[2][4][4];
    #pragma unroll
    for (int i = 0; i < 2; i++)
        #pragma unroll
        for (int j = 0; j < 4; j++)
            #pragma unroll
            for (int v = 0; v < 4; v++) acc[i][j][v] = 0.0f;

    gemm_mainloop(sb, DOUT / 64, aHi, aLo, DOUT, bHi, bLo, DOUT, acc, tid, wid, lane);

    const int len = lengths[b];
    const int wm = (wid & 3) * 32, wn = (wid >> 2) * 32;
    float* prow = gs_f + (size_t)b * SEQ * SEQ;
    #pragma unroll
    for (int i = 0; i < 2; i++) {
        #pragma unroll
        for (int j = 0; j < 4; j++) {
            int gj = n0 + wn + j * 8 + (lane & 3) * 2;
            #pragma unroll
            for (int half = 0; half < 2; half++) {
                int gi = m0 + wm + i * 16 + (lane >> 2) + half * 8;
                float s0 = acc[i][j][half * 2 + 0] * 0.03125f;
                float s1 = acc[i][j][half * 2 + 1] * 0.03125f;
                bool rowbad = (gi >= len);
                if (gj > gi)                 s0 += NEGC;
                if (rowbad || gj >= len)     s0 += NEGC;
                if (gj + 1 > gi)             s1 += NEGC;
                if (rowbad || gj + 1 >= len) s1 += NEGC;
                *reinterpret_cast<float2*>(prow + (size_t)gi * SEQ + gj) =
                    make_float2(s0, s1);
            }
        }
    }
}

// ===========================================================================
// Kernel: row softmax. Row cached in smem; exp computed once; __expf.
// Emits P as bf16 hi/lo (zeros past diagonal up to tile boundary).
// ===========================================================================
__global__ __launch_bounds__(256) void softmax_kernel()
{
    const int i = blockIdx.x;
    const int b = blockIdx.y;
    const float* row = gs_f + ((size_t)b * SEQ + i) * SEQ;
    const int n = i + 1;
    const int nr = ((i >> 7) + 1) << 7;
    __shared__ float buf[SEQ];
    __shared__ float red[8];
    const int tid = threadIdx.x, lane = tid & 31, wrp = tid >> 5;

    float m = -3.4e38f;
    for (int j = tid; j < n; j += 256) {
        float v = row[j];
        buf[j] = v;
        m = fmaxf(m, v);
    }
    #pragma unroll
    for (int o = 16; o; o >>= 1) m = fmaxf(m, __shfl_xor_sync(0xFFFFFFFFu, m, o));
    if (lane == 0) red[wrp] = m;
    __syncthreads();
    if (wrp == 0) {
        float t = red[lane & 7];
        #pragma unroll
        for (int o = 4; o; o >>= 1) t = fmaxf(t, __shfl_xor_sync(0xFFFFFFFFu, t, o));
        if (lane == 0) red[0] = t;
    }
    __syncthreads();
    m = red[0];

    float s = 0.0f;
    for (int j = tid; j < n; j += 256) {
        float e = __expf(buf[j] - m);
        buf[j] = e;
        s += e;
    }
    #pragma unroll
    for (int o = 16; o; o >>= 1) s += __shfl_xor_sync(0xFFFFFFFFu, s, o);
    __syncthreads();
    if (lane == 0) red[wrp] = s;
    __syncthreads();
    if (wrp == 0) {
        float t = red[lane & 7];
        #pragma unroll
        for (int o = 4; o; o >>= 1) t += __shfl_xor_sync(0xFFFFFFFFu, t, o);
        if (lane == 0) red[0] = t;
    }
    __syncthreads();
    const float r = 1.0f / red[0];

    size_t gbase = ((size_t)b * SEQ + i) * SEQ;
    for (int j = tid; j < nr; j += 256) {
        float p = (j < n) ? buf[j] * r : 0.0f;
        __nv_bfloat16 h = __float2bfloat16(p);
        gp_hi[gbase + j] = h;
        gp_lo[gbase + j] = __float2bfloat16(p - __bfloat162float(h));
    }
}

// ===========================================================================
// Kernel: transpose + split V -> Vt (K-major B operand for PV)
// ===========================================================================
__global__ __launch_bounds__(256) void vsplit_kernel()
{
    __shared__ float t[32][33];
    int b = blockIdx.z;
    int n0 = blockIdx.y * 32;
    int j0 = blockIdx.x * 32;
    int tx = threadIdx.x, ty = threadIdx.y;     // (32, 8)
    #pragma unroll
    for (int r = 0; r < 4; r++)
        t[ty + 8 * r][tx] = gv_f[((size_t)b * SEQ + j0 + ty + 8 * r) * DOUT + n0 + tx];
    __syncthreads();
    #pragma unroll
    for (int r = 0; r < 4; r++) {
        int nl = ty + 8 * r;
        float f = t[tx][nl];
        __nv_bfloat16 h = __float2bfloat16(f);
        size_t o = ((size_t)b * DOUT + n0 + nl) * SEQ + j0 + tx;
        gvt_hi[o] = h;
        gvt_lo[o] = __float2bfloat16(f - __bfloat162float(h));
    }
}

// ===========================================================================
// Kernel: O = P @ V  (K bounded by causal extent of the row tile)
// ===========================================================================
__global__ __launch_bounds__(NTHREADS, 2) void pv_mma(float* __restrict__ out)
{
    extern __shared__ char smem[];
    const uint32_t sb = smem_u32(smem);
    const int tid = threadIdx.x, wid = tid >> 5, lane = tid & 31;
    const int b = blockIdx.z;
    const int itile = blockIdx.y;
    const int m0 = itile * 128;
    const int n0 = blockIdx.x * 64;

    const __nv_bfloat16* aHi = gp_hi + ((size_t)b * SEQ + m0) * SEQ;
    const __nv_bfloat16* aLo = gp_lo + ((size_t)b * SEQ + m0) * SEQ;
    const __nv_bfloat16* bHi = gvt_hi + ((size_t)b * DOUT + n0) * SEQ;
    const __nv_bfloat16* bLo = gvt_lo + ((size_t)b * DOUT + n0) * SEQ;

    float acc[2][4][4];
    #pragma unroll
    for (int i = 0; i < 2; i++)
        #pragma unroll
        for (int j = 0; j < 4; j++)
            #pragma unroll
            for (int v = 0; v < 4; v++) acc[i][j][v] = 0.0f;

    gemm_mainloop(sb, (itile + 1) * 2, aHi, aLo, SEQ, bHi, bLo, SEQ, acc, tid, wid, lane);

    const int wm = (wid & 3) * 32, wn = (wid >> 2) * 32;
    #pragma unroll
    for (int i = 0; i < 2; i++) {
        #pragma unroll
        for (int j = 0; j < 4; j++) {
            int col = n0 + wn + j * 8 + (lane & 3) * 2;
            #pragma unroll
            for (int half = 0; half < 2; half++) {
                int m = m0 + wm + i * 16 + (lane >> 2) + half * 8;
                *reinterpret_cast<float2*>(out + ((size_t)b * SEQ + m) * DOUT + col) =
                    make_float2(acc[i][j][half * 2 + 0], acc[i][j][half * 2 + 1]);
            }
        }
    }
}

// ===========================================================================
extern "C" void kernel_launch(void* const* d_in, const int* in_sizes, int n_in,
                              void* d_out, int out_size)
{
    const float* x  = (const float*)d_in[0];
    const float* Wq = (const float*)d_in[1];
    const float* bq = (const float*)d_in[2];
    const float* Wk = (const float*)d_in[3];
    const float* bk = (const float*)d_in[4];
    const float* Wv = (const float*)d_in[5];
    const float* bv = (const float*)d_in[6];
    const int* lengths = (const int*)d_in[7];
    float* out = (float*)d_out;

    static bool attrs_set = false;
    if (!attrs_set) {
        cudaFuncSetAttribute(qkv_mma,    cudaFuncAttributeMaxDynamicSharedMemorySize, SMEM_BYTES);
        cudaFuncSetAttribute(scores_mma, cudaFuncAttributeMaxDynamicSharedMemorySize, SMEM_BYTES);
        cudaFuncSetAttribute(pv_mma,     cudaFuncAttributeMaxDynamicSharedMemorySize, SMEM_BYTES);
        attrs_set = true;
    }

    const int ntot = MTOT * DIN + 3 * DOUT * DIN;        // 11534336, /256 exact
    split_all_kernel<<<ntot / 256, 256>>>(x, Wq, Wk, Wv);

    dim3 g1(DOUT / 64, MTOT / 128, 3);                   // (16, 64, 3)
    qkv_mma<<<g1, NTHREADS, SMEM_BYTES>>>(bq, bk, bv);

    vsplit_kernel<<<dim3(SEQ / 32, DOUT / 32, BATCH), dim3(32, 8)>>>();

    dim3 g2(SEQ / 64, SEQ / 128, BATCH);                 // (32, 16, 4)
    scores_mma<<<g2, NTHREADS, SMEM_BYTES>>>(lengths);

    softmax_kernel<<<dim3(SEQ, BATCH), 256>>>();

    dim3 g4(DOUT / 64, SEQ / 128, BATCH);                // (16, 16, 4)
    pv_mma<<<g4, NTHREADS, SMEM_BYTES>>>(out);
}

// round 16
// speedup vs baseline: 1.7555x; 1.6497x over previous
#include <cuda_runtime.h>
#include <cuda_bf16.h>
#include <cstdint>

#define BATCH 4
#define SEQ   2048
#define DIN   1024
#define DOUT  1024
#define MTOT  (BATCH * SEQ)
#define NEGC  (-1000000000.0f)

// ===========================================================================
// Scratch (device globals — allocations are forbidden)
// ===========================================================================
__device__ __nv_bfloat16 gx_hi[(size_t)MTOT * DIN];
__device__ __nv_bfloat16 gx_lo[(size_t)MTOT * DIN];
__device__ __nv_bfloat16 gw_hi[(size_t)3 * DOUT * DIN];
__device__ __nv_bfloat16 gw_lo[(size_t)3 * DOUT * DIN];
__device__ __nv_bfloat16 gq_hi[(size_t)MTOT * DOUT];
__device__ __nv_bfloat16 gq_lo[(size_t)MTOT * DOUT];
__device__ __nv_bfloat16 gk_hi[(size_t)MTOT * DOUT];
__device__ __nv_bfloat16 gk_lo[(size_t)MTOT * DOUT];
__device__ float         gv_f [(size_t)MTOT * DOUT];
__device__ __nv_bfloat16 gvt_hi[(size_t)BATCH * DOUT * SEQ];
__device__ __nv_bfloat16 gvt_lo[(size_t)BATCH * DOUT * SEQ];
__device__ float         gs_f [(size_t)BATCH * SEQ * SEQ];
__device__ __nv_bfloat16 gp_hi[(size_t)BATCH * SEQ * SEQ];
__device__ __nv_bfloat16 gp_lo[(size_t)BATCH * SEQ * SEQ];

// ===========================================================================
// Base-target PTX helpers (NO tcgen05 — harness compiles for sm_103 base)
// ===========================================================================
__device__ __forceinline__ uint32_t smem_u32(const void* p) {
    uint32_t a;
    asm("{ .reg .u64 t; cvta.to.shared.u64 t, %1; cvt.u32.u64 %0, t; }"
        : "=r"(a) : "l"(p));
    return a;
}

#define CP_ASYNC16(dst, src) \
    asm volatile("cp.async.cg.shared.global [%0], [%1], 16;" \
        :: "r"(dst), "l"(src))
#define CP_COMMIT()  asm volatile("cp.async.commit_group;" ::: "memory")
#define CP_WAIT(N)   asm volatile("cp.async.wait_group %0;" :: "n"(N) : "memory")

__device__ __forceinline__ void ldsm4(uint32_t* r, uint32_t addr) {
    asm volatile("ldmatrix.sync.aligned.m8n8.x4.shared.b16 {%0,%1,%2,%3}, [%4];"
        : "=r"(r[0]), "=r"(r[1]), "=r"(r[2]), "=r"(r[3]) : "r"(addr));
}

__device__ __forceinline__ void mma_bf16(float* c, const uint32_t* a, const uint32_t* b) {
    asm volatile(
        "mma.sync.aligned.m16n8k16.row.col.f32.bf16.bf16.f32 "
        "{%0,%1,%2,%3}, {%4,%5,%6,%7}, {%8,%9}, {%0,%1,%2,%3};"
        : "+f"(c[0]), "+f"(c[1]), "+f"(c[2]), "+f"(c[3])
        : "r"(a[0]), "r"(a[1]), "r"(a[2]), "r"(a[3]), "r"(b[0]), "r"(b[1]));
}

// ===========================================================================
// Shared GEMM engine: 128x64 CTA tile, 8 warps (4m x 2n, 32x32 warp tile),
// BK=64, 2-stage cp.async pipeline, SW128 XOR swizzle, bf16x3 split precision.
// Stage: A_hi(16K) | A_lo(16K) | B_hi(8K) | B_lo(8K) = 48KB; 2 stages = 96KB
// -> 2 CTAs/SM so prologue/epilogue/barrier tails overlap across CTAs.
// ===========================================================================
#define NTHREADS    256
#define STAGE_BYTES 49152
#define SMEM_BYTES  (2 * STAGE_BYTES)    // 98304
#define OFF_AHI     0
#define OFF_ALO     16384
#define OFF_BHI     32768
#define OFF_BLO     40960

__device__ __forceinline__ void fill_stage(
    uint32_t sb, int stage,
    const __nv_bfloat16* aHi, const __nv_bfloat16* aLo, size_t strideA,
    const __nv_bfloat16* bHi, const __nv_bfloat16* bLo, size_t strideB,
    int k0, int tid)
{
    uint32_t base = sb + stage * STAGE_BYTES;
    #pragma unroll
    for (int sub = 0; sub < 2; sub++) {
        const __nv_bfloat16* src = sub ? aLo : aHi;
        uint32_t dst = base + (sub ? OFF_ALO : OFF_AHI);
        #pragma unroll
        for (int t = 0; t < 4; t++) {
            int idx = tid + NTHREADS * t;        // [0,1024)
            int r = idx >> 3;
            int c = idx & 7;
            uint32_t d = dst + (uint32_t)(r * 128 + ((c ^ (r & 7)) << 4));
            CP_ASYNC16(d, src + (size_t)r * strideA + k0 + c * 8);
        }
    }
    #pragma unroll
    for (int sub = 0; sub < 2; sub++) {
        const __nv_bfloat16* src = sub ? bLo : bHi;
        uint32_t dst = base + (sub ? OFF_BLO : OFF_BHI);
        #pragma unroll
        for (int t = 0; t < 2; t++) {
            int idx = tid + NTHREADS * t;        // [0,512)
            int r = idx >> 3;
            int c = idx & 7;
            uint32_t d = dst + (uint32_t)(r * 128 + ((c ^ (r & 7)) << 4));
            CP_ASYNC16(d, src + (size_t)r * strideB + k0 + c * 8);
        }
    }
    CP_COMMIT();
}

// Compute one stage (4 k16-steps, 3 split passes) into acc[2][4][4].
__device__ __forceinline__ void compute_stage(
    uint32_t sb, int stage, float acc[2][4][4], int wid, int lane)
{
    uint32_t base = sb + stage * STAGE_BYTES;
    const int wm = (wid & 3) * 32;
    const int wn = (wid >> 2) * 32;
    #pragma unroll
    for (int ks = 0; ks < 4; ks++) {
        uint32_t aH[2][4], aL[2][4], bH[4][2], bL[4][2];
        #pragma unroll
        for (int i = 0; i < 2; i++) {
            int row = wm + i * 16 + (lane & 15);
            int cb  = ks * 2 + (lane >> 4);
            uint32_t ad = base + (uint32_t)(row * 128 + ((cb ^ (row & 7)) << 4));
            ldsm4(aH[i], ad + OFF_AHI);
            ldsm4(aL[i], ad + OFF_ALO);
        }
        #pragma unroll
        for (int jp = 0; jp < 2; jp++) {
            int g   = lane >> 3;                         // 0..3
            int row = wn + (jp * 2 + (g >> 1)) * 8 + (lane & 7);
            int cb  = ks * 2 + (g & 1);
            uint32_t bd = base + (uint32_t)(row * 128 + ((cb ^ (row & 7)) << 4));
            uint32_t t[4];
            ldsm4(t, bd + OFF_BHI);
            bH[jp*2][0] = t[0]; bH[jp*2][1] = t[1];
            bH[jp*2+1][0] = t[2]; bH[jp*2+1][1] = t[3];
            ldsm4(t, bd + OFF_BLO);
            bL[jp*2][0] = t[0]; bL[jp*2][1] = t[1];
            bL[jp*2+1][0] = t[2]; bL[jp*2+1][1] = t[3];
        }
        #pragma unroll
        for (int i = 0; i < 2; i++)
            #pragma unroll
            for (int j = 0; j < 4; j++) {
                mma_bf16(acc[i][j], aH[i], bH[j]);
                mma_bf16(acc[i][j], aH[i], bL[j]);
                mma_bf16(acc[i][j], aL[i], bH[j]);
            }
    }
}

// 2-stage K loop; trailing sync makes the refill race-safe.
__device__ __forceinline__ void gemm_mainloop(
    uint32_t sb, int nch,
    const __nv_bfloat16* aHi, const __nv_bfloat16* aLo, size_t strideA,
    const __nv_bfloat16* bHi, const __nv_bfloat16* bLo, size_t strideB,
    float acc[2][4][4], int tid, int wid, int lane)
{
    fill_stage(sb, 0, aHi, aLo, strideA, bHi, bLo, strideB, 0, tid);
    for (int ch = 0; ch < nch; ch++) {
        if (ch + 1 < nch) {
            fill_stage(sb, (ch + 1) & 1, aHi, aLo, strideA, bHi, bLo, strideB,
                       (ch + 1) * 64, tid);
            CP_WAIT(1);
        } else {
            CP_WAIT(0);
        }
        __syncthreads();
        compute_stage(sb, ch & 1, acc, wid, lane);
        __syncthreads();
    }
}

// ===========================================================================
// Kernel: merged split fp32 -> bf16 (hi, lo) for x, Wq, Wk, Wv (one launch)
// ===========================================================================
__global__ __launch_bounds__(256) void split_all_kernel(
    const float* __restrict__ x,  const float* __restrict__ Wq,
    const float* __restrict__ Wk, const float* __restrict__ Wv)
{
    const int nx = MTOT * DIN;
    const int nw = DOUT * DIN;
    int i = blockIdx.x * 256 + threadIdx.x;
    const float* src; __nv_bfloat16 *hi, *lo; int idx;
    if (i < nx) {
        src = x; idx = i; hi = gx_hi; lo = gx_lo;
    } else {
        int t = i - nx;
        int z = t / nw;
        idx = t - z * nw;
        src = (z == 0) ? Wq : (z == 1) ? Wk : Wv;
        hi = gw_hi + (size_t)z * nw;
        lo = gw_lo + (size_t)z * nw;
    }
    float f = src[idx];
    __nv_bfloat16 h = __float2bfloat16(f);
    hi[idx] = h;
    lo[idx] = __float2bfloat16(f - __bfloat162float(h));
}

// ===========================================================================
// Kernel: QKV projection.  z selects Q/K/V.  n-tile is 64 wide.
// Q/K row-tiles with all rows >= len[b] are skipped: Q rows >= len are only
// read by skipped scores tiles; K rows >= len only contribute to NEG-masked
// columns, and the skipped region stays ZERO forever (device globals are
// zero-init and never written) so s=0 is absorbed exactly by the mask.
// ===========================================================================
__global__ __launch_bounds__(NTHREADS, 2) void qkv_mma(
    const float* __restrict__ bq, const float* __restrict__ bk,
    const float* __restrict__ bv, const int* __restrict__ lengths)
{
    const int z = blockIdx.z;
    const int m0 = blockIdx.y * 128;
    if (z < 2) {
        int b  = m0 >> 11;            // /SEQ
        int s0 = m0 & (SEQ - 1);
        if (s0 >= lengths[b]) return; // whole tile invalid for Q/K
    }
    extern __shared__ char smem[];
    const uint32_t sb = smem_u32(smem);
    const int tid = threadIdx.x, wid = tid >> 5, lane = tid & 31;
    const int n0 = blockIdx.x * 64;

    const __nv_bfloat16* aHi = gx_hi + (size_t)m0 * DIN;
    const __nv_bfloat16* aLo = gx_lo + (size_t)m0 * DIN;
    size_t woff = (size_t)z * DOUT * DIN + (size_t)n0 * DIN;
    const __nv_bfloat16* bHi = gw_hi + woff;
    const __nv_bfloat16* bLo = gw_lo + woff;
    const float* bias = (z == 0) ? bq : (z == 1) ? bk : bv;

    float acc[2][4][4];
    #pragma unroll
    for (int i = 0; i < 2; i++)
        #pragma unroll
        for (int j = 0; j < 4; j++)
            #pragma unroll
            for (int v = 0; v < 4; v++) acc[i][j][v] = 0.0f;

    gemm_mainloop(sb, DIN / 64, aHi, aLo, DIN, bHi, bLo, DIN, acc, tid, wid, lane);

    const int wm = (wid & 3) * 32, wn = (wid >> 2) * 32;
    #pragma unroll
    for (int i = 0; i < 2; i++) {
        #pragma unroll
        for (int j = 0; j < 4; j++) {
            int col = n0 + wn + j * 8 + (lane & 3) * 2;
            float b0 = bias[col], b1 = bias[col + 1];
            #pragma unroll
            for (int half = 0; half < 2; half++) {
                int m = m0 + wm + i * 16 + (lane >> 2) + half * 8;
                float v0 = acc[i][j][half * 2 + 0] + b0;
                float v1 = acc[i][j][half * 2 + 1] + b1;
                if (z < 2) {
                    __nv_bfloat16 h0 = __float2bfloat16(v0);
                    __nv_bfloat16 h1 = __float2bfloat16(v1);
                    __nv_bfloat16 l0 = __float2bfloat16(v0 - __bfloat162float(h0));
                    __nv_bfloat16 l1 = __float2bfloat16(v1 - __bfloat162float(h1));
                    __nv_bfloat16* oh = (z == 0) ? gq_hi : gk_hi;
                    __nv_bfloat16* ol = (z == 0) ? gq_lo : gk_lo;
                    uint32_t ph, pl;
                    {
                        uint16_t a16 = __bfloat16_as_ushort(h0), b16 = __bfloat16_as_ushort(h1);
                        ph = (uint32_t)a16 | ((uint32_t)b16 << 16);
                        a16 = __bfloat16_as_ushort(l0); b16 = __bfloat16_as_ushort(l1);
                        pl = (uint32_t)a16 | ((uint32_t)b16 << 16);
                    }
                    *reinterpret_cast<uint32_t*>(oh + (size_t)m * DOUT + col) = ph;
                    *reinterpret_cast<uint32_t*>(ol + (size_t)m * DOUT + col) = pl;
                } else {
                    *reinterpret_cast<float2*>(gv_f + (size_t)m * DOUT + col) =
                        make_float2(v0, v1);
                }
            }
        }
    }
}

// ===========================================================================
// Kernel: scores = (Q.K^T)/32 + masks  (skips tiles above diagonal AND
// row-tiles fully >= len[b]: those rows' softmax is the exact uniform
// shortcut and never reads the scores)
// ===========================================================================
__global__ __launch_bounds__(NTHREADS, 2) void scores_mma(const int* __restrict__ lengths)
{
    const int m0 = blockIdx.y * 128;
    const int n0 = blockIdx.x * 64;
    if (n0 > m0 + 127) return;
    const int b = blockIdx.z;
    const int len = lengths[b];
    if (m0 >= len) return;                    // rows never read by softmax
    extern __shared__ char smem[];
    const uint32_t sb = smem_u32(smem);
    const int tid = threadIdx.x, wid = tid >> 5, lane = tid & 31;

    const __nv_bfloat16* aHi = gq_hi + ((size_t)b * SEQ + m0) * DOUT;
    const __nv_bfloat16* aLo = gq_lo + ((size_t)b * SEQ + m0) * DOUT;
    const __nv_bfloat16* bHi = gk_hi + ((size_t)b * SEQ + n0) * DOUT;
    const __nv_bfloat16* bLo = gk_lo + ((size_t)b * SEQ + n0) * DOUT;

    float acc[2][4][4];
    #pragma unroll
    for (int i = 0; i < 2; i++)
        #pragma unroll
        for (int j = 0; j < 4; j++)
            #pragma unroll
            for (int v = 0; v < 4; v++) acc[i][j][v] = 0.0f;

    gemm_mainloop(sb, DOUT / 64, aHi, aLo, DOUT, bHi, bLo, DOUT, acc, tid, wid, lane);

    const int wm = (wid & 3) * 32, wn = (wid >> 2) * 32;
    float* prow = gs_f + (size_t)b * SEQ * SEQ;
    #pragma unroll
    for (int i = 0; i < 2; i++) {
        #pragma unroll
        for (int j = 0; j < 4; j++) {
            int gj = n0 + wn + j * 8 + (lane & 3) * 2;
            #pragma unroll
            for (int half = 0; half < 2; half++) {
                int gi = m0 + wm + i * 16 + (lane >> 2) + half * 8;
                float s0 = acc[i][j][half * 2 + 0] * 0.03125f;
                float s1 = acc[i][j][half * 2 + 1] * 0.03125f;
                bool rowbad = (gi >= len);
                if (gj > gi)                 s0 += NEGC;
                if (rowbad || gj >= len)     s0 += NEGC;
                if (gj + 1 > gi)             s1 += NEGC;
                if (rowbad || gj + 1 >= len) s1 += NEGC;
                *reinterpret_cast<float2*>(prow + (size_t)gi * SEQ + gj) =
                    make_float2(s0, s1);
            }
        }
    }
}

// ===========================================================================
// Kernel: row softmax. Rows i >= len take the exact uniform shortcut
// (all masked entries are exactly NEG -> exp(0)=1, sum=i+1, p=1/(i+1) —
// bit-identical to the exp path and to the reference). Valid rows: smem
// cache, single exp, __expf.
// ===========================================================================
__global__ __launch_bounds__(256) void softmax_kernel(const int* __restrict__ lengths)
{
    const int i = blockIdx.x;
    const int b = blockIdx.y;
    const int n = i + 1;
    const int nr = ((i >> 7) + 1) << 7;
    const int tid = threadIdx.x, lane = tid & 31, wrp = tid >> 5;
    size_t gbase = ((size_t)b * SEQ + i) * SEQ;

    const int len = lengths[b];
    if (i >= len) {
        // exact uniform: p = 1/(i+1) for j <= i, 0 beyond (up to tile bound)
        float inv = 1.0f / (float)n;
        __nv_bfloat16 h = __float2bfloat16(inv);
        __nv_bfloat16 l = __float2bfloat16(inv - __bfloat162float(h));
        for (int j = tid; j < nr; j += 256) {
            bool in = (j < n);
            gp_hi[gbase + j] = in ? h : __nv_bfloat16(0.0f);
            gp_lo[gbase + j] = in ? l : __nv_bfloat16(0.0f);
        }
        return;
    }

    const float* row = gs_f + gbase;
    __shared__ float buf[SEQ];
    __shared__ float red[8];

    float m = -3.4e38f;
    for (int j = tid; j < n; j += 256) {
        float v = row[j];
        buf[j] = v;
        m = fmaxf(m, v);
    }
    #pragma unroll
    for (int o = 16; o; o >>= 1) m = fmaxf(m, __shfl_xor_sync(0xFFFFFFFFu, m, o));
    if (lane == 0) red[wrp] = m;
    __syncthreads();
    if (wrp == 0) {
        float t = red[lane & 7];
        #pragma unroll
        for (int o = 4; o; o >>= 1) t = fmaxf(t, __shfl_xor_sync(0xFFFFFFFFu, t, o));
        if (lane == 0) red[0] = t;
    }
    __syncthreads();
    m = red[0];

    float s = 0.0f;
    for (int j = tid; j < n; j += 256) {
        float e = __expf(buf[j] - m);
        buf[j] = e;
        s += e;
    }
    #pragma unroll
    for (int o = 16; o; o >>= 1) s += __shfl_xor_sync(0xFFFFFFFFu, s, o);
    __syncthreads();
    if (lane == 0) red[wrp] = s;
    __syncthreads();
    if (wrp == 0) {
        float t = red[lane & 7];
        #pragma unroll
        for (int o = 4; o; o >>= 1) t += __shfl_xor_sync(0xFFFFFFFFu, t, o);
        if (lane == 0) red[0] = t;
    }
    __syncthreads();
    const float r = 1.0f / red[0];

    for (int j = tid; j < nr; j += 256) {
        float p = (j < n) ? buf[j] * r : 0.0f;
        __nv_bfloat16 h = __float2bfloat16(p);
        gp_hi[gbase + j] = h;
        gp_lo[gbase + j] = __float2bfloat16(p - __bfloat162float(h));
    }
}

// ===========================================================================
// Kernel: transpose + split V -> Vt (K-major B operand for PV)
// ===========================================================================
__global__ __launch_bounds__(256) void vsplit_kernel()
{
    __shared__ float t[32][33];
    int b = blockIdx.z;
    int n0 = blockIdx.y * 32;
    int j0 = blockIdx.x * 32;
    int tx = threadIdx.x, ty = threadIdx.y;     // (32, 8)
    #pragma unroll
    for (int r = 0; r < 4; r++)
        t[ty + 8 * r][tx] = gv_f[((size_t)b * SEQ + j0 + ty + 8 * r) * DOUT + n0 + tx];
    __syncthreads();
    #pragma unroll
    for (int r = 0; r < 4; r++) {
        int nl = ty + 8 * r;
        float f = t[tx][nl];
        __nv_bfloat16 h = __float2bfloat16(f);
        size_t o = ((size_t)b * DOUT + n0 + nl) * SEQ + j0 + tx;
        gvt_hi[o] = h;
        gvt_lo[o] = __float2bfloat16(f - __bfloat162float(h));
    }
}

// ===========================================================================
// Kernel: O = P @ V  (K bounded by causal extent of the row tile)
// ===========================================================================
__global__ __launch_bounds__(NTHREADS, 2) void pv_mma(float* __restrict__ out)
{
    extern __shared__ char smem[];
    const uint32_t sb = smem_u32(smem);
    const int tid = threadIdx.x, wid = tid >> 5, lane = tid & 31;
    const int b = blockIdx.z;
    const int itile = blockIdx.y;
    const int m0 = itile * 128;
    const int n0 = blockIdx.x * 64;

    const __nv_bfloat16* aHi = gp_hi + ((size_t)b * SEQ + m0) * SEQ;
    const __nv_bfloat16* aLo = gp_lo + ((size_t)b * SEQ + m0) * SEQ;
    const __nv_bfloat16* bHi = gvt_hi + ((size_t)b * DOUT + n0) * SEQ;
    const __nv_bfloat16* bLo = gvt_lo + ((size_t)b * DOUT + n0) * SEQ;

    float acc[2][4][4];
    #pragma unroll
    for (int i = 0; i < 2; i++)
        #pragma unroll
        for (int j = 0; j < 4; j++)
            #pragma unroll
            for (int v = 0; v < 4; v++) acc[i][j][v] = 0.0f;

    gemm_mainloop(sb, (itile + 1) * 2, aHi, aLo, SEQ, bHi, bLo, SEQ, acc, tid, wid, lane);

    const int wm = (wid & 3) * 32, wn = (wid >> 2) * 32;
    #pragma unroll
    for (int i = 0; i < 2; i++) {
        #pragma unroll
        for (int j = 0; j < 4; j++) {
            int col = n0 + wn + j * 8 + (lane & 3) * 2;
            #pragma unroll
            for (int half = 0; half < 2; half++) {
                int m = m0 + wm + i * 16 + (lane >> 2) + half * 8;
                *reinterpret_cast<float2*>(out + ((size_t)b * SEQ + m) * DOUT + col) =
                    make_float2(acc[i][j][half * 2 + 0], acc[i][j][half * 2 + 1]);
            }
        }
    }
}

// ===========================================================================
extern "C" void kernel_launch(void* const* d_in, const int* in_sizes, int n_in,
                              void* d_out, int out_size)
{
    const float* x  = (const float*)d_in[0];
    const float* Wq = (const float*)d_in[1];
    const float* bq = (const float*)d_in[2];
    const float* Wk = (const float*)d_in[3];
    const float* bk = (const float*)d_in[4];
    const float* Wv = (const float*)d_in[5];
    const float* bv = (const float*)d_in[6];
    const int* lengths = (const int*)d_in[7];
    float* out = (float*)d_out;

    static bool attrs_set = false;
    if (!attrs_set) {
        cudaFuncSetAttribute(qkv_mma,    cudaFuncAttributeMaxDynamicSharedMemorySize, SMEM_BYTES);
        cudaFuncSetAttribute(scores_mma, cudaFuncAttributeMaxDynamicSharedMemorySize, SMEM_BYTES);
        cudaFuncSetAttribute(pv_mma,     cudaFuncAttributeMaxDynamicSharedMemorySize, SMEM_BYTES);
        attrs_set = true;
    }

    const int ntot = MTOT * DIN + 3 * DOUT * DIN;        // 11534336, /256 exact
    split_all_kernel<<<ntot / 256, 256>>>(x, Wq, Wk, Wv);

    dim3 g1(DOUT / 64, MTOT / 128, 3);                   // (16, 64, 3)
    qkv_mma<<<g1, NTHREADS, SMEM_BYTES>>>(bq, bk, bv, lengths);

    vsplit_kernel<<<dim3(SEQ / 32, DOUT / 32, BATCH), dim3(32, 8)>>>();

    dim3 g2(SEQ / 64, SEQ / 128, BATCH);                 // (32, 16, 4)
    scores_mma<<<g2, NTHREADS, SMEM_BYTES>>>(lengths);

    softmax_kernel<<<dim3(SEQ, BATCH), 256>>>(lengths);

    dim3 g4(DOUT / 64, SEQ / 128, BATCH);                // (16, 16, 4)
    pv_mma<<<g4, NTHREADS, SMEM_BYTES>>>(out);
}

// round 17
// speedup vs baseline: 2.0178x; 1.1494x over previous
#include <cuda_runtime.h>
#include <cuda_fp16.h>
#include <cstdint>

#define BATCH 4
#define SEQ   2048
#define DIN   1024
#define DOUT  1024
#define MTOT  (BATCH * SEQ)
#define NEGC  (-1000000000.0f)

// ===========================================================================
// Scratch (device globals — allocations are forbidden; zero-initialized)
// ===========================================================================
__device__ __half gx_hi[(size_t)MTOT * DIN];
__device__ __half gx_lo[(size_t)MTOT * DIN];
__device__ __half gw_hi[(size_t)3 * DOUT * DIN];
__device__ __half gw_lo[(size_t)3 * DOUT * DIN];
__device__ __half gq_h [(size_t)MTOT * DOUT];          // Q: single plane
__device__ __half gk_hi[(size_t)MTOT * DOUT];
__device__ __half gk_lo[(size_t)MTOT * DOUT];
__device__ float  gv_f [(size_t)MTOT * DOUT];
__device__ __half gvt_hi[(size_t)BATCH * DOUT * SEQ];
__device__ __half gvt_lo[(size_t)BATCH * DOUT * SEQ];
__device__ float  gs_f [(size_t)BATCH * SEQ * SEQ];
__device__ __half gp_h [(size_t)BATCH * SEQ * SEQ];    // P: single plane

// ===========================================================================
// Base-target PTX helpers (NO tcgen05 — harness compiles for sm_103 base)
// ===========================================================================
__device__ __forceinline__ uint32_t smem_u32(const void* p) {
    uint32_t a;
    asm("{ .reg .u64 t; cvta.to.shared.u64 t, %1; cvt.u32.u64 %0, t; }"
        : "=r"(a) : "l"(p));
    return a;
}

#define CP_ASYNC16(dst, src) \
    asm volatile("cp.async.cg.shared.global [%0], [%1], 16;" \
        :: "r"(dst), "l"(src))
#define CP_COMMIT()  asm volatile("cp.async.commit_group;" ::: "memory")
#define CP_WAIT(N)   asm volatile("cp.async.wait_group %0;" :: "n"(N) : "memory")

__device__ __forceinline__ void ldsm4(uint32_t* r, uint32_t addr) {
    asm volatile("ldmatrix.sync.aligned.m8n8.x4.shared.b16 {%0,%1,%2,%3}, [%4];"
        : "=r"(r[0]), "=r"(r[1]), "=r"(r[2]), "=r"(r[3]) : "r"(addr));
}

__device__ __forceinline__ void mma_fp16(float* c, const uint32_t* a, const uint32_t* b) {
    asm volatile(
        "mma.sync.aligned.m16n8k16.row.col.f32.f16.f16.f32 "
        "{%0,%1,%2,%3}, {%4,%5,%6,%7}, {%8,%9}, {%0,%1,%2,%3};"
        : "+f"(c[0]), "+f"(c[1]), "+f"(c[2]), "+f"(c[3])
        : "r"(a[0]), "r"(a[1]), "r"(a[2]), "r"(a[3]), "r"(b[0]), "r"(b[1]));
}

__device__ __forceinline__ uint32_t pack2(float v0, float v1) {
    uint16_t a = __half_as_ushort(__float2half_rn(v0));
    uint16_t b = __half_as_ushort(__float2half_rn(v1));
    return (uint32_t)a | ((uint32_t)b << 16);
}

// ===========================================================================
// Engine geometry: 128x64 CTA tile, 8 warps (4m x 2n, 32x32 warp tile),
// BK=64, 2-stage cp.async pipeline, SW128 XOR swizzle.
// SYM (3-pass, A hi/lo + B hi/lo): stage 48KB -> 96KB (qkv)
// ASYM (2-pass, A single + B hi/lo): stage 32KB -> 64KB (scores, pv)
// ===========================================================================
#define NTHREADS     256
// sym layout
#define S_STAGE      49152
#define S_AHI        0
#define S_ALO        16384
#define S_BHI        32768
#define S_BLO        40960
#define SMEM_SYM     (2 * S_STAGE)     // 98304
// asym layout
#define A_STAGE      32768
#define A_A          0
#define A_BHI        16384
#define A_BLO        24576
#define SMEM_ASYM    (2 * A_STAGE)     // 65536

// ---------------- SYM (qkv) ----------------
__device__ __forceinline__ void fill_sym(
    uint32_t sb, int stage,
    const __half* aHi, const __half* aLo, size_t strideA,
    const __half* bHi, const __half* bLo, size_t strideB,
    int k0, int tid)
{
    uint32_t base = sb + stage * S_STAGE;
    #pragma unroll
    for (int sub = 0; sub < 2; sub++) {
        const __half* src = sub ? aLo : aHi;
        uint32_t dst = base + (sub ? S_ALO : S_AHI);
        #pragma unroll
        for (int t = 0; t < 4; t++) {
            int idx = tid + NTHREADS * t;        // [0,1024)
            int r = idx >> 3, c = idx & 7;
            uint32_t d = dst + (uint32_t)(r * 128 + ((c ^ (r & 7)) << 4));
            CP_ASYNC16(d, src + (size_t)r * strideA + k0 + c * 8);
        }
    }
    #pragma unroll
    for (int sub = 0; sub < 2; sub++) {
        const __half* src = sub ? bLo : bHi;
        uint32_t dst = base + (sub ? S_BLO : S_BHI);
        #pragma unroll
        for (int t = 0; t < 2; t++) {
            int idx = tid + NTHREADS * t;        // [0,512)
            int r = idx >> 3, c = idx & 7;
            uint32_t d = dst + (uint32_t)(r * 128 + ((c ^ (r & 7)) << 4));
            CP_ASYNC16(d, src + (size_t)r * strideB + k0 + c * 8);
        }
    }
    CP_COMMIT();
}

__device__ __forceinline__ void compute_sym(
    uint32_t sb, int stage, float acc[2][4][4], int wid, int lane)
{
    uint32_t base = sb + stage * S_STAGE;
    const int wm = (wid & 3) * 32;
    const int wn = (wid >> 2) * 32;
    #pragma unroll
    for (int ks = 0; ks < 4; ks++) {
        uint32_t aH[2][4], aL[2][4], bH[4][2], bL[4][2];
        #pragma unroll
        for (int i = 0; i < 2; i++) {
            int row = wm + i * 16 + (lane & 15);
            int cb  = ks * 2 + (lane >> 4);
            uint32_t ad = base + (uint32_t)(row * 128 + ((cb ^ (row & 7)) << 4));
            ldsm4(aH[i], ad + S_AHI);
            ldsm4(aL[i], ad + S_ALO);
        }
        #pragma unroll
        for (int jp = 0; jp < 2; jp++) {
            int g   = lane >> 3;
            int row = wn + (jp * 2 + (g >> 1)) * 8 + (lane & 7);
            int cb  = ks * 2 + (g & 1);
            uint32_t bd = base + (uint32_t)(row * 128 + ((cb ^ (row & 7)) << 4));
            uint32_t t[4];
            ldsm4(t, bd + S_BHI);
            bH[jp*2][0] = t[0]; bH[jp*2][1] = t[1];
            bH[jp*2+1][0] = t[2]; bH[jp*2+1][1] = t[3];
            ldsm4(t, bd + S_BLO);
            bL[jp*2][0] = t[0]; bL[jp*2][1] = t[1];
            bL[jp*2+1][0] = t[2]; bL[jp*2+1][1] = t[3];
        }
        #pragma unroll
        for (int i = 0; i < 2; i++)
            #pragma unroll
            for (int j = 0; j < 4; j++) {
                mma_fp16(acc[i][j], aH[i], bH[j]);
                mma_fp16(acc[i][j], aH[i], bL[j]);
                mma_fp16(acc[i][j], aL[i], bH[j]);
            }
    }
}

__device__ __forceinline__ void loop_sym(
    uint32_t sb, int nch,
    const __half* aHi, const __half* aLo, size_t strideA,
    const __half* bHi, const __half* bLo, size_t strideB,
    float acc[2][4][4], int tid, int wid, int lane)
{
    fill_sym(sb, 0, aHi, aLo, strideA, bHi, bLo, strideB, 0, tid);
    for (int ch = 0; ch < nch; ch++) {
        if (ch + 1 < nch) {
            fill_sym(sb, (ch + 1) & 1, aHi, aLo, strideA, bHi, bLo, strideB,
                     (ch + 1) * 64, tid);
            CP_WAIT(1);
        } else {
            CP_WAIT(0);
        }
        __syncthreads();
        compute_sym(sb, ch & 1, acc, wid, lane);
        __syncthreads();
    }
}

// ---------------- ASYM (scores, pv) ----------------
__device__ __forceinline__ void fill_asym(
    uint32_t sb, int stage,
    const __half* a, size_t strideA,
    const __half* bHi, const __half* bLo, size_t strideB,
    int k0, int tid)
{
    uint32_t base = sb + stage * A_STAGE;
    #pragma unroll
    for (int t = 0; t < 4; t++) {
        int idx = tid + NTHREADS * t;            // [0,1024)
        int r = idx >> 3, c = idx & 7;
        uint32_t d = base + A_A + (uint32_t)(r * 128 + ((c ^ (r & 7)) << 4));
        CP_ASYNC16(d, a + (size_t)r * strideA + k0 + c * 8);
    }
    #pragma unroll
    for (int sub = 0; sub < 2; sub++) {
        const __half* src = sub ? bLo : bHi;
        uint32_t dst = base + (sub ? A_BLO : A_BHI);
        #pragma unroll
        for (int t = 0; t < 2; t++) {
            int idx = tid + NTHREADS * t;        // [0,512)
            int r = idx >> 3, c = idx & 7;
            uint32_t d = dst + (uint32_t)(r * 128 + ((c ^ (r & 7)) << 4));
            CP_ASYNC16(d, src + (size_t)r * strideB + k0 + c * 8);
        }
    }
    CP_COMMIT();
}

__device__ __forceinline__ void compute_asym(
    uint32_t sb, int stage, float acc[2][4][4], int wid, int lane)
{
    uint32_t base = sb + stage * A_STAGE;
    const int wm = (wid & 3) * 32;
    const int wn = (wid >> 2) * 32;
    #pragma unroll
    for (int ks = 0; ks < 4; ks++) {
        uint32_t aF[2][4], bH[4][2], bL[4][2];
        #pragma unroll
        for (int i = 0; i < 2; i++) {
            int row = wm + i * 16 + (lane & 15);
            int cb  = ks * 2 + (lane >> 4);
            uint32_t ad = base + A_A + (uint32_t)(row * 128 + ((cb ^ (row & 7)) << 4));
            ldsm4(aF[i], ad);
        }
        #pragma unroll
        for (int jp = 0; jp < 2; jp++) {
            int g   = lane >> 3;
            int row = wn + (jp * 2 + (g >> 1)) * 8 + (lane & 7);
            int cb  = ks * 2 + (g & 1);
            uint32_t bd = base + (uint32_t)(row * 128 + ((cb ^ (row & 7)) << 4));
            uint32_t t[4];
            ldsm4(t, bd + A_BHI);
            bH[jp*2][0] = t[0]; bH[jp*2][1] = t[1];
            bH[jp*2+1][0] = t[2]; bH[jp*2+1][1] = t[3];
            ldsm4(t, bd + A_BLO);
            bL[jp*2][0] = t[0]; bL[jp*2][1] = t[1];
            bL[jp*2+1][0] = t[2]; bL[jp*2+1][1] = t[3];
        }
        #pragma unroll
        for (int i = 0; i < 2; i++)
            #pragma unroll
            for (int j = 0; j < 4; j++) {
                mma_fp16(acc[i][j], aF[i], bH[j]);
                mma_fp16(acc[i][j], aF[i], bL[j]);
            }
    }
}

__device__ __forceinline__ void loop_asym(
    uint32_t sb, int nch,
    const __half* a, size_t strideA,
    const __half* bHi, const __half* bLo, size_t strideB,
    float acc[2][4][4], int tid, int wid, int lane)
{
    fill_asym(sb, 0, a, strideA, bHi, bLo, strideB, 0, tid);
    for (int ch = 0; ch < nch; ch++) {
        if (ch + 1 < nch) {
            fill_asym(sb, (ch + 1) & 1, a, strideA, bHi, bLo, strideB,
                      (ch + 1) * 64, tid);
            CP_WAIT(1);
        } else {
            CP_WAIT(0);
        }
        __syncthreads();
        compute_asym(sb, ch & 1, acc, wid, lane);
        __syncthreads();
    }
}

// ===========================================================================
// Kernel: merged split fp32 -> fp16 (hi, lo) for x, Wq, Wk, Wv (one launch)
// ===========================================================================
__global__ __launch_bounds__(256) void split_all_kernel(
    const float* __restrict__ x,  const float* __restrict__ Wq,
    const float* __restrict__ Wk, const float* __restrict__ Wv)
{
    const int nx = MTOT * DIN;
    const int nw = DOUT * DIN;
    int i = blockIdx.x * 256 + threadIdx.x;
    const float* src; __half *hi, *lo; int idx;
    if (i < nx) {
        src = x; idx = i; hi = gx_hi; lo = gx_lo;
    } else {
        int t = i - nx;
        int z = t / nw;
        idx = t - z * nw;
        src = (z == 0) ? Wq : (z == 1) ? Wk : Wv;
        hi = gw_hi + (size_t)z * nw;
        lo = gw_lo + (size_t)z * nw;
    }
    float f = src[idx];
    __half h = __float2half_rn(f);
    hi[idx] = h;
    lo[idx] = __float2half_rn(f - __half2float(h));
}

// ===========================================================================
// Kernel: QKV projection (3-pass sym, fp16).  z selects Q/K/V.
// Q/K row-tiles fully >= len[b] are skipped (see round-13 analysis; skipped
// K region stays zero forever so s=0 is absorbed exactly by the NEG mask).
// Q written as a SINGLE fp16 plane (scores is asym), K as hi/lo, V as f32.
// ===========================================================================
__global__ __launch_bounds__(NTHREADS, 2) void qkv_mma(
    const float* __restrict__ bq, const float* __restrict__ bk,
    const float* __restrict__ bv, const int* __restrict__ lengths)
{
    const int z = blockIdx.z;
    const int m0 = blockIdx.y * 128;
    if (z < 2) {
        int b  = m0 >> 11;
        int s0 = m0 & (SEQ - 1);
        if (s0 >= lengths[b]) return;
    }
    extern __shared__ char smem[];
    const uint32_t sb = smem_u32(smem);
    const int tid = threadIdx.x, wid = tid >> 5, lane = tid & 31;
    const int n0 = blockIdx.x * 64;

    const __half* aHi = gx_hi + (size_t)m0 * DIN;
    const __half* aLo = gx_lo + (size_t)m0 * DIN;
    size_t woff = (size_t)z * DOUT * DIN + (size_t)n0 * DIN;
    const __half* bHi = gw_hi + woff;
    const __half* bLo = gw_lo + woff;
    const float* bias = (z == 0) ? bq : (z == 1) ? bk : bv;

    float acc[2][4][4];
    #pragma unroll
    for (int i = 0; i < 2; i++)
        #pragma unroll
        for (int j = 0; j < 4; j++)
            #pragma unroll
            for (int v = 0; v < 4; v++) acc[i][j][v] = 0.0f;

    loop_sym(sb, DIN / 64, aHi, aLo, DIN, bHi, bLo, DIN, acc, tid, wid, lane);

    const int wm = (wid & 3) * 32, wn = (wid >> 2) * 32;
    #pragma unroll
    for (int i = 0; i < 2; i++) {
        #pragma unroll
        for (int j = 0; j < 4; j++) {
            int col = n0 + wn + j * 8 + (lane & 3) * 2;
            float b0 = bias[col], b1 = bias[col + 1];
            #pragma unroll
            for (int half = 0; half < 2; half++) {
                int m = m0 + wm + i * 16 + (lane >> 2) + half * 8;
                float v0 = acc[i][j][half * 2 + 0] + b0;
                float v1 = acc[i][j][half * 2 + 1] + b1;
                if (z == 0) {
                    *reinterpret_cast<uint32_t*>(gq_h + (size_t)m * DOUT + col) =
                        pack2(v0, v1);
                } else if (z == 1) {
                    __half h0 = __float2half_rn(v0);
                    __half h1 = __float2half_rn(v1);
                    float  l0 = v0 - __half2float(h0);
                    float  l1 = v1 - __half2float(h1);
                    uint32_t ph = (uint32_t)__half_as_ushort(h0)
                                | ((uint32_t)__half_as_ushort(h1) << 16);
                    *reinterpret_cast<uint32_t*>(gk_hi + (size_t)m * DOUT + col) = ph;
                    *reinterpret_cast<uint32_t*>(gk_lo + (size_t)m * DOUT + col) =
                        pack2(l0, l1);
                } else {
                    *reinterpret_cast<float2*>(gv_f + (size_t)m * DOUT + col) =
                        make_float2(v0, v1);
                }
            }
        }
    }
}

// ===========================================================================
// Kernel: scores = (Q.K^T)/32 + masks  (2-pass asym: A=q single, B=k hi/lo).
// Skips tiles above the diagonal AND row-tiles fully >= len[b].
// ===========================================================================
__global__ __launch_bounds__(NTHREADS, 2) void scores_mma(const int* __restrict__ lengths)
{
    const int m0 = blockIdx.y * 128;
    const int n0 = blockIdx.x * 64;
    if (n0 > m0 + 127) return;
    const int b = blockIdx.z;
    const int len = lengths[b];
    if (m0 >= len) return;
    extern __shared__ char smem[];
    const uint32_t sb = smem_u32(smem);
    const int tid = threadIdx.x, wid = tid >> 5, lane = tid & 31;

    const __half* a   = gq_h  + ((size_t)b * SEQ + m0) * DOUT;
    const __half* bHi = gk_hi + ((size_t)b * SEQ + n0) * DOUT;
    const __half* bLo = gk_lo + ((size_t)b * SEQ + n0) * DOUT;

    float acc[2][4][4];
    #pragma unroll
    for (int i = 0; i < 2; i++)
        #pragma unroll
        for (int j = 0; j < 4; j++)
            #pragma unroll
            for (int v = 0; v < 4; v++) acc[i][j][v] = 0.0f;

    loop_asym(sb, DOUT / 64, a, DOUT, bHi, bLo, DOUT, acc, tid, wid, lane);

    const int wm = (wid & 3) * 32, wn = (wid >> 2) * 32;
    float* prow = gs_f + (size_t)b * SEQ * SEQ;
    #pragma unroll
    for (int i = 0; i < 2; i++) {
        #pragma unroll
        for (int j = 0; j < 4; j++) {
            int gj = n0 + wn + j * 8 + (lane & 3) * 2;
            #pragma unroll
            for (int half = 0; half < 2; half++) {
                int gi = m0 + wm + i * 16 + (lane >> 2) + half * 8;
                float s0 = acc[i][j][half * 2 + 0] * 0.03125f;
                float s1 = acc[i][j][half * 2 + 1] * 0.03125f;
                bool rowbad = (gi >= len);
                if (gj > gi)                 s0 += NEGC;
                if (rowbad || gj >= len)     s0 += NEGC;
                if (gj + 1 > gi)             s1 += NEGC;
                if (rowbad || gj + 1 >= len) s1 += NEGC;
                *reinterpret_cast<float2*>(prow + (size_t)gi * SEQ + gj) =
                    make_float2(s0, s1);
            }
        }
    }
}

// ===========================================================================
// Kernel: row softmax -> P as SINGLE fp16 plane.
// Rows i >= len: store p = 1.0 (exact); pv rescales by 1/(i+1) in fp32.
// Valid rows: smem cache, single __expf pass.
// ===========================================================================
__global__ __launch_bounds__(256) void softmax_kernel(const int* __restrict__ lengths)
{
    const int i = blockIdx.x;
    const int b = blockIdx.y;
    const int n = i + 1;
    const int nr = ((i >> 7) + 1) << 7;
    const int tid = threadIdx.x, lane = tid & 31, wrp = tid >> 5;
    size_t gbase = ((size_t)b * SEQ + i) * SEQ;

    const int len = lengths[b];
    if (i >= len) {
        const __half one  = __float2half_rn(1.0f);
        const __half zero = __ushort_as_half(0);
        for (int j = tid; j < nr; j += 256)
            gp_h[gbase + j] = (j < n) ? one : zero;
        return;
    }

    const float* row = gs_f + gbase;
    __shared__ float buf[SEQ];
    __shared__ float red[8];

    float m = -3.4e38f;
    for (int j = tid; j < n; j += 256) {
        float v = row[j];
        buf[j] = v;
        m = fmaxf(m, v);
    }
    #pragma unroll
    for (int o = 16; o; o >>= 1) m = fmaxf(m, __shfl_xor_sync(0xFFFFFFFFu, m, o));
    if (lane == 0) red[wrp] = m;
    __syncthreads();
    if (wrp == 0) {
        float t = red[lane & 7];
        #pragma unroll
        for (int o = 4; o; o >>= 1) t = fmaxf(t, __shfl_xor_sync(0xFFFFFFFFu, t, o));
        if (lane == 0) red[0] = t;
    }
    __syncthreads();
    m = red[0];

    float s = 0.0f;
    for (int j = tid; j < n; j += 256) {
        float e = __expf(buf[j] - m);
        buf[j] = e;
        s += e;
    }
    #pragma unroll
    for (int o = 16; o; o >>= 1) s += __shfl_xor_sync(0xFFFFFFFFu, s, o);
    __syncthreads();
    if (lane == 0) red[wrp] = s;
    __syncthreads();
    if (wrp == 0) {
        float t = red[lane & 7];
        #pragma unroll
        for (int o = 4; o; o >>= 1) t += __shfl_xor_sync(0xFFFFFFFFu, t, o);
        if (lane == 0) red[0] = t;
    }
    __syncthreads();
    const float r = 1.0f / red[0];

    for (int j = tid; j < nr; j += 256) {
        float p = (j < n) ? buf[j] * r : 0.0f;
        gp_h[gbase + j] = __float2half_rn(p);
    }
}

// ===========================================================================
// Kernel: transpose + split V -> Vt fp16 hi/lo (K-major B operand for PV)
// ===========================================================================
__global__ __launch_bounds__(256) void vsplit_kernel()
{
    __shared__ float t[32][33];
    int b = blockIdx.z;
    int n0 = blockIdx.y * 32;
    int j0 = blockIdx.x * 32;
    int tx = threadIdx.x, ty = threadIdx.y;     // (32, 8)
    #pragma unroll
    for (int r = 0; r < 4; r++)
        t[ty + 8 * r][tx] = gv_f[((size_t)b * SEQ + j0 + ty + 8 * r) * DOUT + n0 + tx];
    __syncthreads();
    #pragma unroll
    for (int r = 0; r < 4; r++) {
        int nl = ty + 8 * r;
        float f = t[tx][nl];
        __half h = __float2half_rn(f);
        size_t o = ((size_t)b * DOUT + n0 + nl) * SEQ + j0 + tx;
        gvt_hi[o] = h;
        gvt_lo[o] = __float2half_rn(f - __half2float(h));
    }
}

// ===========================================================================
// Kernel: O = P @ V (2-pass asym: A=P single, B=Vt hi/lo).
// K bounded by causal extent; rows m >= len rescaled by 1/(m+1) (P held 1.0).
// ===========================================================================
__global__ __launch_bounds__(NTHREADS, 2) void pv_mma(
    float* __restrict__ out, const int* __restrict__ lengths)
{
    extern __shared__ char smem[];
    const uint32_t sb = smem_u32(smem);
    const int tid = threadIdx.x, wid = tid >> 5, lane = tid & 31;
    const int b = blockIdx.z;
    const int itile = blockIdx.y;
    const int m0 = itile * 128;
    const int n0 = blockIdx.x * 64;
    const int len = lengths[b];

    const __half* a   = gp_h   + ((size_t)b * SEQ + m0) * SEQ;
    const __half* bHi = gvt_hi + ((size_t)b * DOUT + n0) * SEQ;
    const __half* bLo = gvt_lo + ((size_t)b * DOUT + n0) * SEQ;

    float acc[2][4][4];
    #pragma unroll
    for (int i = 0; i < 2; i++)
        #pragma unroll
        for (int j = 0; j < 4; j++)
            #pragma unroll
            for (int v = 0; v < 4; v++) acc[i][j][v] = 0.0f;

    loop_asym(sb, (itile + 1) * 2, a, SEQ, bHi, bLo, SEQ, acc, tid, wid, lane);

    const int wm = (wid & 3) * 32, wn = (wid >> 2) * 32;
    #pragma unroll
    for (int i = 0; i < 2; i++) {
        #pragma unroll
        for (int j = 0; j < 4; j++) {
            int col = n0 + wn + j * 8 + (lane & 3) * 2;
            #pragma unroll
            for (int half = 0; half < 2; half++) {
                int m = m0 + wm + i * 16 + (lane >> 2) + half * 8;
                float sc = (m >= len) ? (1.0f / (float)(m + 1)) : 1.0f;
                *reinterpret_cast<float2*>(out + ((size_t)b * SEQ + m) * DOUT + col) =
                    make_float2(acc[i][j][half * 2 + 0] * sc,
                                acc[i][j][half * 2 + 1] * sc);
            }
        }
    }
}

// ===========================================================================
extern "C" void kernel_launch(void* const* d_in, const int* in_sizes, int n_in,
                              void* d_out, int out_size)
{
    const float* x  = (const float*)d_in[0];
    const float* Wq = (const float*)d_in[1];
    const float* bq = (const float*)d_in[2];
    const float* Wk = (const float*)d_in[3];
    const float* bk = (const float*)d_in[4];
    const float* Wv = (const float*)d_in[5];
    const float* bv = (const float*)d_in[6];
    const int* lengths = (const int*)d_in[7];
    float* out = (float*)d_out;

    static bool attrs_set = false;
    if (!attrs_set) {
        cudaFuncSetAttribute(qkv_mma,    cudaFuncAttributeMaxDynamicSharedMemorySize, SMEM_SYM);
        cudaFuncSetAttribute(scores_mma, cudaFuncAttributeMaxDynamicSharedMemorySize, SMEM_ASYM);
        cudaFuncSetAttribute(pv_mma,     cudaFuncAttributeMaxDynamicSharedMemorySize, SMEM_ASYM);
        attrs_set = true;
    }

    const int ntot = MTOT * DIN + 3 * DOUT * DIN;        // 11534336, /256 exact
    split_all_kernel<<<ntot / 256, 256>>>(x, Wq, Wk, Wv);

    dim3 g1(DOUT / 64, MTOT / 128, 3);                   // (16, 64, 3)
    qkv_mma<<<g1, NTHREADS, SMEM_SYM>>>(bq, bk, bv, lengths);

    vsplit_kernel<<<dim3(SEQ / 32, DOUT / 32, BATCH), dim3(32, 8)>>>();

    dim3 g2(SEQ / 64, SEQ / 128, BATCH);                 // (32, 16, 4)
    scores_mma<<<g2, NTHREADS, SMEM_ASYM>>>(lengths);

    softmax_kernel<<<dim3(SEQ, BATCH), 256>>>(lengths);

    dim3 g4(DOUT / 64, SEQ / 128, BATCH);                // (16, 16, 4)
    pv_mma<<<g4, NTHREADS, SMEM_ASYM>>>(out, lengths);
}